// round 1
// baseline (speedup 1.0000x reference)
#include <cuda_runtime.h>
#include <cuda_bf16.h>
#include <math.h>

// Problem constants
#define BB 2
#define TT 1024
#define DD 1024
#define HH 16
#define HD 64
#define FF_ 4096
#define LL 8
#define VV 32000
#define MM (BB*TT)   // 2048

// ---------------- scratch (static device globals; allocation-free) -------------
__device__ float g_x  [MM * DD];        // residual stream   (8 MB)
__device__ float g_h  [MM * DD];        // LN output         (8 MB)
__device__ float g_qkv[MM * 3 * DD];    // qkv               (24 MB)
__device__ float g_att[MM * DD];        // attention output  (8 MB)
__device__ float g_m1 [MM * FF_];       // mlp hidden        (32 MB)

// ---------------- embed: x = tok_emb[idx] + sinusoidal PE ----------------------
__global__ void embed_kernel(const int* __restrict__ idx,
                             const float* __restrict__ emb,
                             float* __restrict__ x)
{
    int bt  = blockIdx.x;              // 0..2047
    int t   = bt & (TT - 1);
    int tok = idx[bt];
    int c0  = threadIdx.x * 4;         // 256 threads * 4 = 1024
    const float kfac = -9.210340371976184f / (float)DD; // -ln(10000)/D
#pragma unroll
    for (int u = 0; u < 4; ++u) {
        int c  = c0 + u;
        int i2 = c & ~1;
        float freq = expf((float)i2 * kfac);
        float ang  = (float)t * freq;
        float pe   = (c & 1) ? cosf(ang) : sinf(ang);
        x[(size_t)bt * DD + c] = emb[(size_t)tok * DD + c] + pe;
    }
}

// ---------------- layernorm (one block per row, D=1024) ------------------------
__global__ void ln_kernel(const float* __restrict__ x,
                          const float* __restrict__ s,
                          const float* __restrict__ b,
                          float* __restrict__ y)
{
    int row = blockIdx.x, tid = threadIdx.x;
    const float4* xr = (const float4*)(x + (size_t)row * DD);
    float4 v = xr[tid];
    float sum = v.x + v.y + v.z + v.w;
    float sq  = v.x*v.x + v.y*v.y + v.z*v.z + v.w*v.w;
#pragma unroll
    for (int o = 16; o > 0; o >>= 1) {
        sum += __shfl_xor_sync(0xffffffffu, sum, o);
        sq  += __shfl_xor_sync(0xffffffffu, sq,  o);
    }
    __shared__ float ssum[8], ssq[8];
    int warp = tid >> 5, lane = tid & 31;
    if (lane == 0) { ssum[warp] = sum; ssq[warp] = sq; }
    __syncthreads();
    if (tid < 32) {
        float a = (tid < 8) ? ssum[tid] : 0.f;
        float c = (tid < 8) ? ssq [tid] : 0.f;
#pragma unroll
        for (int o = 4; o > 0; o >>= 1) {
            a += __shfl_xor_sync(0xffffffffu, a, o);
            c += __shfl_xor_sync(0xffffffffu, c, o);
        }
        if (tid == 0) { ssum[0] = a; ssq[0] = c; }
    }
    __syncthreads();
    float mean = ssum[0] * (1.f / DD);
    float var  = ssq[0]  * (1.f / DD) - mean * mean;
    float rstd = rsqrtf(var + 1e-5f);
    float4 sv = ((const float4*)s)[tid];
    float4 bv = ((const float4*)b)[tid];
    float4 o;
    o.x = (v.x - mean) * rstd * sv.x + bv.x;
    o.y = (v.y - mean) * rstd * sv.y + bv.y;
    o.z = (v.z - mean) * rstd * sv.z + bv.z;
    o.w = (v.w - mean) * rstd * sv.w + bv.w;
    ((float4*)(y + (size_t)row * DD))[tid] = o;
}

// ---------------- SGEMM: C[M,N] = A[M,K] @ W[K,N] (+bias) (+epilogue) ----------
// EPI: 0 = +bias, 1 = +bias then exact GELU, 2 = +bias +res, 3 = plain
__device__ __forceinline__ float gelu_exact(float x) {
    return 0.5f * x * (1.f + erff(x * 0.7071067811865475f));
}

template<int EPI>
__global__ void __launch_bounds__(256)
sgemm_kernel(const float* __restrict__ A, const float* __restrict__ W,
             const float* __restrict__ bias, const float* __restrict__ res,
             float* __restrict__ C, int M, int N, int K)
{
    constexpr int BM = 128, BN = 128, BK = 16;
    constexpr int AST = BM + 4;                 // padded stride for As
    __shared__ float As[BK][AST];
    __shared__ float Bs[BK][BN];

    const int tid = threadIdx.x;
    const int tx  = tid & 15;       // 16 col groups
    const int ty  = tid >> 4;       // 16 row groups
    const int bm  = blockIdx.y * BM;
    const int bn  = blockIdx.x * BN;

    float acc[8][8] = {};

    for (int k0 = 0; k0 < K; k0 += BK) {
        // A tile 128x16 -> As[k][m] (transposed)
#pragma unroll
        for (int l = 0; l < 2; ++l) {
            int f = tid + l * 256;
            int r = f >> 2;
            int c = (f & 3) << 2;
            float4 v = *(const float4*)&A[(size_t)(bm + r) * K + k0 + c];
            As[c + 0][r] = v.x; As[c + 1][r] = v.y;
            As[c + 2][r] = v.z; As[c + 3][r] = v.w;
        }
        // B tile 16x128 -> Bs[k][n]
#pragma unroll
        for (int l = 0; l < 2; ++l) {
            int f = tid + l * 256;
            int r = f >> 5;
            int c = (f & 31) << 2;
            *(float4*)&Bs[r][c] = *(const float4*)&W[(size_t)(k0 + r) * N + bn + c];
        }
        __syncthreads();
#pragma unroll
        for (int kk = 0; kk < BK; ++kk) {
            float a[8], b[8];
            *(float4*)&a[0] = *(const float4*)&As[kk][ty * 8];
            *(float4*)&a[4] = *(const float4*)&As[kk][ty * 8 + 4];
            *(float4*)&b[0] = *(const float4*)&Bs[kk][tx * 8];
            *(float4*)&b[4] = *(const float4*)&Bs[kk][tx * 8 + 4];
#pragma unroll
            for (int i = 0; i < 8; ++i)
#pragma unroll
                for (int j = 0; j < 8; ++j)
                    acc[i][j] += a[i] * b[j];
        }
        __syncthreads();
    }

    const int row0 = bm + ty * 8;
    const int col0 = bn + tx * 8;
    float bb[8];
    if (EPI != 3) {
        *(float4*)&bb[0] = *(const float4*)&bias[col0];
        *(float4*)&bb[4] = *(const float4*)&bias[col0 + 4];
    }
#pragma unroll
    for (int i = 0; i < 8; ++i) {
        int row = row0 + i;
        float rr[8];
        if (EPI == 2) {
            *(float4*)&rr[0] = *(const float4*)&res[(size_t)row * N + col0];
            *(float4*)&rr[4] = *(const float4*)&res[(size_t)row * N + col0 + 4];
        }
        float out[8];
#pragma unroll
        for (int j = 0; j < 8; ++j) {
            float v = acc[i][j];
            if (EPI != 3) v += bb[j];
            if (EPI == 1) v = gelu_exact(v);
            if (EPI == 2) v += rr[j];
            out[j] = v;
        }
        *(float4*)&C[(size_t)row * N + col0]     = *(float4*)&out[0];
        *(float4*)&C[(size_t)row * N + col0 + 4] = *(float4*)&out[4];
    }
}

// ---------------- fused causal attention (flash-style) -------------------------
// grid: (T/128, B*H), 256 threads. smem: Q[128x64], K[64x64], V[64x64], P[128x64]
#define ASTR 68
#define ATT_SMEM ((128 + 64 + 64 + 128) * ASTR * 4)

__global__ void __launch_bounds__(256)
attn_kernel(const float* __restrict__ qkv, float* __restrict__ out)
{
    extern __shared__ float sm[];
    float* Qs = sm;                   // 128 x ASTR
    float* Ks = Qs + 128 * ASTR;      //  64 x ASTR
    float* Vs = Ks +  64 * ASTR;      //  64 x ASTR
    float* Ps = Vs +  64 * ASTR;      // 128 x ASTR

    const int tid = threadIdx.x;
    const int bh  = blockIdx.y;
    const int b   = bh >> 4;
    const int hh  = bh & 15;
    const int q0  = blockIdx.x * 128;
    const int tx  = tid & 7;          // 8 col groups
    const int ty  = tid >> 3;         // 32 row groups
    const int r0  = ty * 4;
    const int c0  = tx * 8;

    // load Q tile [128 x 64]
    const float* qbase = qkv + ((size_t)(b * TT + q0)) * (3 * DD) + hh * HD;
#pragma unroll
    for (int l = 0; l < 8; ++l) {
        int f = tid + l * 256;
        int r = f >> 4;
        int c = (f & 15) << 2;
        *(float4*)&Qs[r * ASTR + c] = *(const float4*)(qbase + (size_t)r * (3 * DD) + c);
    }

    float m[4], lsum[4], O[4][8];
#pragma unroll
    for (int i = 0; i < 4; ++i) {
        m[i] = -1e30f; lsum[i] = 0.f;
#pragma unroll
        for (int j = 0; j < 8; ++j) O[i][j] = 0.f;
    }

    const int ntiles = blockIdx.x * 2 + 2;     // causal: kv up to q0+127
    for (int t = 0; t < ntiles; ++t) {
        const int j0 = t * 64;
        __syncthreads();   // protect K/V/P reuse
        const float* kbase = qkv + ((size_t)(b * TT + j0)) * (3 * DD) + DD + hh * HD;
        const float* vbase = kbase + DD;
#pragma unroll
        for (int l = 0; l < 4; ++l) {
            int f = tid + l * 256;
            int r = f >> 4;
            int c = (f & 15) << 2;
            *(float4*)&Ks[r * ASTR + c] = *(const float4*)(kbase + (size_t)r * (3 * DD) + c);
            *(float4*)&Vs[r * ASTR + c] = *(const float4*)(vbase + (size_t)r * (3 * DD) + c);
        }
        __syncthreads();

        // S = Q @ K^T  (per-thread 4x8)
        float s[4][8] = {};
#pragma unroll
        for (int k4 = 0; k4 < 16; ++k4) {
            float4 qv[4];
#pragma unroll
            for (int i = 0; i < 4; ++i)
                qv[i] = *(const float4*)&Qs[(r0 + i) * ASTR + k4 * 4];
#pragma unroll
            for (int j = 0; j < 8; ++j) {
                float4 kv = *(const float4*)&Ks[(c0 + j) * ASTR + k4 * 4];
#pragma unroll
                for (int i = 0; i < 4; ++i)
                    s[i][j] += qv[i].x * kv.x + qv[i].y * kv.y
                             + qv[i].z * kv.z + qv[i].w * kv.w;
            }
        }

        const bool needmask = (j0 + 63 > q0);  // only diagonal tiles
#pragma unroll
        for (int i = 0; i < 4; ++i)
#pragma unroll
            for (int j = 0; j < 8; ++j) {
                float v = s[i][j] * 0.125f;    // 1/sqrt(64)
                if (needmask && (j0 + c0 + j > q0 + r0 + i)) v = -1e30f;
                s[i][j] = v;
            }

        // row max across j then across the 8 tx lanes
        float tm[4];
#pragma unroll
        for (int i = 0; i < 4; ++i) {
            float mx = s[i][0];
#pragma unroll
            for (int j = 1; j < 8; ++j) mx = fmaxf(mx, s[i][j]);
            tm[i] = mx;
        }
#pragma unroll
        for (int o = 1; o < 8; o <<= 1)
#pragma unroll
            for (int i = 0; i < 4; ++i)
                tm[i] = fmaxf(tm[i], __shfl_xor_sync(0xffffffffu, tm[i], o));

        float corr[4], ts[4];
#pragma unroll
        for (int i = 0; i < 4; ++i) {
            float mn = fmaxf(m[i], tm[i]);
            corr[i] = expf(m[i] - mn);
            m[i] = mn;
            ts[i] = 0.f;
#pragma unroll
            for (int j = 0; j < 8; ++j) {
                float p = expf(s[i][j] - mn);
                s[i][j] = p;
                ts[i] += p;
            }
        }
#pragma unroll
        for (int o = 1; o < 8; o <<= 1)
#pragma unroll
            for (int i = 0; i < 4; ++i)
                ts[i] += __shfl_xor_sync(0xffffffffu, ts[i], o);
#pragma unroll
        for (int i = 0; i < 4; ++i) {
            lsum[i] = lsum[i] * corr[i] + ts[i];
#pragma unroll
            for (int j = 0; j < 8; ++j) O[i][j] *= corr[i];
        }

        // stage P
#pragma unroll
        for (int i = 0; i < 4; ++i) {
            *(float4*)&Ps[(r0 + i) * ASTR + c0]     = make_float4(s[i][0], s[i][1], s[i][2], s[i][3]);
            *(float4*)&Ps[(r0 + i) * ASTR + c0 + 4] = make_float4(s[i][4], s[i][5], s[i][6], s[i][7]);
        }
        __syncthreads();

        // O += P @ V
#pragma unroll
        for (int k4 = 0; k4 < 16; ++k4) {
            float p[4][4];
#pragma unroll
            for (int i = 0; i < 4; ++i) {
                float4 pv = *(const float4*)&Ps[(r0 + i) * ASTR + k4 * 4];
                p[i][0] = pv.x; p[i][1] = pv.y; p[i][2] = pv.z; p[i][3] = pv.w;
            }
#pragma unroll
            for (int u = 0; u < 4; ++u) {
                int kv = k4 * 4 + u;
                float4 va = *(const float4*)&Vs[kv * ASTR + c0];
                float4 vb = *(const float4*)&Vs[kv * ASTR + c0 + 4];
#pragma unroll
                for (int i = 0; i < 4; ++i) {
                    float pi = p[i][u];
                    O[i][0] += pi * va.x; O[i][1] += pi * va.y;
                    O[i][2] += pi * va.z; O[i][3] += pi * va.w;
                    O[i][4] += pi * vb.x; O[i][5] += pi * vb.y;
                    O[i][6] += pi * vb.z; O[i][7] += pi * vb.w;
                }
            }
        }
    }

    // write normalized O
#pragma unroll
    for (int i = 0; i < 4; ++i) {
        float inv = 1.f / lsum[i];
        int qg = q0 + r0 + i;
        float* dst = out + ((size_t)(b * TT + qg)) * DD + hh * HD + c0;
        float4 oa = make_float4(O[i][0] * inv, O[i][1] * inv, O[i][2] * inv, O[i][3] * inv);
        float4 ob = make_float4(O[i][4] * inv, O[i][5] * inv, O[i][6] * inv, O[i][7] * inv);
        *(float4*)dst       = oa;
        *(float4*)(dst + 4) = ob;
    }
}

// ---------------- launch ---------------------------------------------------------
extern "C" void kernel_launch(void* const* d_in, const int* in_sizes, int n_in,
                              void* d_out, int out_size)
{
    const int*   idx     = (const int*)  d_in[0];
    const float* tok_emb = (const float*)d_in[1];
    const float* ln1_s   = (const float*)d_in[2];
    const float* ln1_b   = (const float*)d_in[3];
    const float* qkv_w   = (const float*)d_in[4];
    const float* qkv_b   = (const float*)d_in[5];
    const float* out_w   = (const float*)d_in[6];
    const float* out_b   = (const float*)d_in[7];
    const float* ln2_s   = (const float*)d_in[8];
    const float* ln2_b   = (const float*)d_in[9];
    const float* mlp_w1  = (const float*)d_in[10];
    const float* mlp_b1  = (const float*)d_in[11];
    const float* mlp_w2  = (const float*)d_in[12];
    const float* mlp_b2  = (const float*)d_in[13];
    const float* lnf_s   = (const float*)d_in[14];
    const float* lnf_b   = (const float*)d_in[15];
    const float* head_w  = (const float*)d_in[16];
    float* logits = (float*)d_out;

    float *x, *h, *qkv, *att, *m1;
    cudaGetSymbolAddress((void**)&x,   g_x);
    cudaGetSymbolAddress((void**)&h,   g_h);
    cudaGetSymbolAddress((void**)&qkv, g_qkv);
    cudaGetSymbolAddress((void**)&att, g_att);
    cudaGetSymbolAddress((void**)&m1,  g_m1);

    cudaFuncSetAttribute(attn_kernel, cudaFuncAttributeMaxDynamicSharedMemorySize, ATT_SMEM);

    embed_kernel<<<MM, 256>>>(idx, tok_emb, x);

    for (int l = 0; l < LL; ++l) {
        ln_kernel<<<MM, 256>>>(x, ln1_s + (size_t)l * DD, ln1_b + (size_t)l * DD, h);

        sgemm_kernel<0><<<dim3(3 * DD / 128, MM / 128), 256>>>(
            h, qkv_w + (size_t)l * DD * 3 * DD, qkv_b + (size_t)l * 3 * DD,
            nullptr, qkv, MM, 3 * DD, DD);

        attn_kernel<<<dim3(TT / 128, BB * HH), 256, ATT_SMEM>>>(qkv, att);

        sgemm_kernel<2><<<dim3(DD / 128, MM / 128), 256>>>(
            att, out_w + (size_t)l * DD * DD, out_b + (size_t)l * DD,
            x, x, MM, DD, DD);

        ln_kernel<<<MM, 256>>>(x, ln2_s + (size_t)l * DD, ln2_b + (size_t)l * DD, h);

        sgemm_kernel<1><<<dim3(FF_ / 128, MM / 128), 256>>>(
            h, mlp_w1 + (size_t)l * DD * FF_, mlp_b1 + (size_t)l * FF_,
            nullptr, m1, MM, FF_, DD);

        sgemm_kernel<2><<<dim3(DD / 128, MM / 128), 256>>>(
            m1, mlp_w2 + (size_t)l * FF_ * DD, mlp_b2 + (size_t)l * DD,
            x, x, MM, DD, FF_);
    }

    ln_kernel<<<MM, 256>>>(x, lnf_s, lnf_b, h);

    sgemm_kernel<3><<<dim3(VV / 128, MM / 128), 256>>>(
        h, head_w, nullptr, nullptr, logits, MM, VV, DD);
}

// round 3
// speedup vs baseline: 1.3602x; 1.3602x over previous
#include <cuda_runtime.h>
#include <cuda_bf16.h>
#include <math.h>
#include <stdint.h>

// Problem constants
#define BB 2
#define TT 1024
#define DD 1024
#define HH 16
#define HD 64
#define FF_ 4096
#define LL 8
#define VV 32000
#define MM (BB*TT)   // 2048

typedef __nv_bfloat16 bf16;

// ---------------- scratch (static device globals; allocation-free) -------------
__device__ float g_x   [MM * DD];          // residual stream (fp32)
__device__ float g_qkv [MM * 3 * DD];      // qkv (fp32)
__device__ bf16  g_ahi [MM * DD];          // activation hi (LN out / attn out)
__device__ bf16  g_alo [MM * DD];          // activation lo
__device__ bf16  g_m1hi[MM * FF_];         // mlp hidden hi
__device__ bf16  g_m1lo[MM * FF_];         // mlp hidden lo

// transposed + bf16-split weights, [N,K] row-major per matrix
#define LW      12582912ULL
#define OFF_OUT 3145728ULL
#define OFF_M1  4194304ULL
#define OFF_M2  8388608ULL
#define OFF_HD  100663296ULL
#define WTOT    133431296ULL
__device__ bf16 g_wh[WTOT];
__device__ bf16 g_wl[WTOT];

// ---------------- helpers -------------------------------------------------------
__device__ __forceinline__ uint32_t smem_u32(const void* p) {
    uint32_t a;
    asm("{ .reg .u64 t; cvta.to.shared.u64 t, %1; cvt.u32.u64 %0, t; }" : "=r"(a) : "l"(p));
    return a;
}
__device__ __forceinline__ void cp_async16(uint32_t saddr, const void* gaddr) {
    asm volatile("cp.async.cg.shared.global [%0], [%1], 16;" :: "r"(saddr), "l"(gaddr));
}
__device__ __forceinline__ void cp_commit() { asm volatile("cp.async.commit_group;"); }
template<int N>
__device__ __forceinline__ void cp_wait() { asm volatile("cp.async.wait_group %0;" :: "n"(N)); }

__device__ __forceinline__ void ldsm4(uint32_t& r0, uint32_t& r1, uint32_t& r2, uint32_t& r3,
                                      uint32_t addr) {
    asm volatile("ldmatrix.sync.aligned.m8n8.x4.shared.b16 {%0,%1,%2,%3}, [%4];"
                 : "=r"(r0), "=r"(r1), "=r"(r2), "=r"(r3) : "r"(addr));
}
__device__ __forceinline__ void mma_bf16(float* d, const uint32_t* a, const uint32_t* b) {
    asm volatile(
        "mma.sync.aligned.m16n8k16.row.col.f32.bf16.bf16.f32 "
        "{%0,%1,%2,%3}, {%4,%5,%6,%7}, {%8,%9}, {%0,%1,%2,%3};"
        : "+f"(d[0]), "+f"(d[1]), "+f"(d[2]), "+f"(d[3])
        : "r"(a[0]), "r"(a[1]), "r"(a[2]), "r"(a[3]), "r"(b[0]), "r"(b[1]));
}
__device__ __forceinline__ uint32_t bf2pack(float a, float b) {
    __nv_bfloat162 t = __floats2bfloat162_rn(a, b);
    return *(uint32_t*)&t;
}
__device__ __forceinline__ void split2(float v, bf16& h, bf16& l) {
    h = __float2bfloat16_rn(v);
    l = __float2bfloat16_rn(v - __bfloat162float(h));
}
__device__ __forceinline__ float gelu_exact(float x) {
    return 0.5f * x * (1.f + erff(x * 0.7071067811865475f));
}

// ---------------- embed ---------------------------------------------------------
__global__ void embed_kernel(const int* __restrict__ idx,
                             const float* __restrict__ emb,
                             float* __restrict__ x)
{
    int bt  = blockIdx.x;
    int t   = bt & (TT - 1);
    int tok = idx[bt];
    int c0  = threadIdx.x * 4;
    const float kfac = -9.210340371976184f / (float)DD;
#pragma unroll
    for (int u = 0; u < 4; ++u) {
        int c  = c0 + u;
        int i2 = c & ~1;
        float freq = expf((float)i2 * kfac);
        float ang  = (float)t * freq;
        float pe   = (c & 1) ? cosf(ang) : sinf(ang);
        x[(size_t)bt * DD + c] = emb[(size_t)tok * DD + c] + pe;
    }
}

// ---------------- layernorm -> bf16 hi/lo pair -----------------------------------
__global__ void ln_kernel(const float* __restrict__ x,
                          const float* __restrict__ s,
                          const float* __restrict__ b,
                          bf16* __restrict__ yhi,
                          bf16* __restrict__ ylo)
{
    int row = blockIdx.x, tid = threadIdx.x;
    const float4* xr = (const float4*)(x + (size_t)row * DD);
    float4 v = xr[tid];
    float sum = v.x + v.y + v.z + v.w;
    float sq  = v.x*v.x + v.y*v.y + v.z*v.z + v.w*v.w;
#pragma unroll
    for (int o = 16; o > 0; o >>= 1) {
        sum += __shfl_xor_sync(0xffffffffu, sum, o);
        sq  += __shfl_xor_sync(0xffffffffu, sq,  o);
    }
    __shared__ float ssum[8], ssq[8];
    int warp = tid >> 5, lane = tid & 31;
    if (lane == 0) { ssum[warp] = sum; ssq[warp] = sq; }
    __syncthreads();
    if (tid < 32) {
        float a = (tid < 8) ? ssum[tid] : 0.f;
        float c = (tid < 8) ? ssq [tid] : 0.f;
#pragma unroll
        for (int o = 4; o > 0; o >>= 1) {
            a += __shfl_xor_sync(0xffffffffu, a, o);
            c += __shfl_xor_sync(0xffffffffu, c, o);
        }
        if (tid == 0) { ssum[0] = a; ssq[0] = c; }
    }
    __syncthreads();
    float mean = ssum[0] * (1.f / DD);
    float var  = ssq[0]  * (1.f / DD) - mean * mean;
    float rstd = rsqrtf(var + 1e-5f);
    float4 sv = ((const float4*)s)[tid];
    float4 bv = ((const float4*)b)[tid];
    float o0 = (v.x - mean) * rstd * sv.x + bv.x;
    float o1 = (v.y - mean) * rstd * sv.y + bv.y;
    float o2 = (v.z - mean) * rstd * sv.z + bv.z;
    float o3 = (v.w - mean) * rstd * sv.w + bv.w;
    bf16 h0,l0,h1,l1,h2,l2,h3,l3;
    split2(o0,h0,l0); split2(o1,h1,l1); split2(o2,h2,l2); split2(o3,h3,l3);
    uint2 hp, lp;
    hp.x = bf2pack(__bfloat162float(h0), __bfloat162float(h1));
    hp.y = bf2pack(__bfloat162float(h2), __bfloat162float(h3));
    lp.x = bf2pack(__bfloat162float(l0), __bfloat162float(l1));
    lp.y = bf2pack(__bfloat162float(l2), __bfloat162float(l3));
    *(uint2*)&yhi[(size_t)row * DD + tid * 4] = hp;
    *(uint2*)&ylo[(size_t)row * DD + tid * 4] = lp;
}

// ---------------- weight transpose + bf16 split: W[K,N] -> {hi,lo}[N,K] ----------
__global__ void wconv_kernel(const float* __restrict__ W,
                             bf16* __restrict__ Thi, bf16* __restrict__ Tlo,
                             int K, int N)
{
    __shared__ float tile[32][33];
    int n0 = blockIdx.x * 32, k0 = blockIdx.y * 32;
    int tx = threadIdx.x, ty = threadIdx.y;
#pragma unroll
    for (int j = 0; j < 32; j += 8)
        tile[ty + j][tx] = W[(size_t)(k0 + ty + j) * N + n0 + tx];
    __syncthreads();
#pragma unroll
    for (int j = 0; j < 32; j += 8) {
        float v = tile[tx][ty + j];
        bf16 hi, lo;
        split2(v, hi, lo);
        size_t o = (size_t)(n0 + ty + j) * K + k0 + tx;
        Thi[o] = hi; Tlo[o] = lo;
    }
}

// ---------------- bf16x3 GEMM on mma.sync ----------------------------------------
// C[M,N] = A[M,K] @ W[N,K]^T with A = Ahi+Alo, W = Whi+Wlo (drop lo*lo)
// EPI: 0 = +bias -> C(f32) ; 1 = +bias,GELU -> split (Chi,Clo) ; 2 = +bias+res -> C ; 3 = plain -> C
#define GBK 32
#define GSTR 40                      // smem row stride in bf16 elems (80 B)
#define GTILEB (128 * GSTR * 2)      // 10240 B per tile
#define GSTAGES 3
#define GSMEM (GSTAGES * 2 * GTILEB) // 61440 B

template<int EPI>
__global__ void __launch_bounds__(256, 2)
gemm_mma(const bf16* __restrict__ Ahi, const bf16* __restrict__ Alo,
         const bf16* __restrict__ Whi, const bf16* __restrict__ Wlo,
         const float* __restrict__ bias, const float* __restrict__ res,
         float* __restrict__ C, bf16* __restrict__ Chi, bf16* __restrict__ Clo,
         int N, int K)
{
    extern __shared__ char smraw[];
    const uint32_t sbase = smem_u32(smraw);

    const int tid  = threadIdx.x;
    const int wid  = tid >> 5, lane = tid & 31;
    const int bm   = blockIdx.y * 128, bn = blockIdx.x * 128;
    const int wm   = (wid >> 2) * 64;      // warp M offset (0/64)
    const int wn   = (wid & 3) * 32;       // warp N offset (0/32/64/96)

    const int S = (3 * K) / GBK;

    // per-thread load decomposition: chunks c = tid, tid+256 for A and for B
    const int r0c = tid >> 2, c0e = (tid & 3) * 8;               // chunk tid
    const int r1c = (tid + 256) >> 2, c1e = ((tid + 256) & 3) * 8;

#define LDSTAGE(sidx)                                                              \
    do {                                                                           \
        int _kg = (sidx) * GBK;                                                    \
        int _seg = _kg / K, _ko = _kg - _seg * K;                                  \
        const bf16* _As = (_seg < 2) ? Ahi : Alo;                                  \
        const bf16* _Ws = (_seg == 1) ? Wlo : Whi;                                 \
        uint32_t _sa = sbase + ((sidx) % GSTAGES) * 2 * GTILEB;                    \
        uint32_t _sb = _sa + GTILEB;                                               \
        cp_async16(_sa + r0c * 80 + (c0e * 2), _As + (size_t)(bm + r0c) * K + _ko + c0e); \
        cp_async16(_sa + r1c * 80 + (c1e * 2), _As + (size_t)(bm + r1c) * K + _ko + c1e); \
        cp_async16(_sb + r0c * 80 + (c0e * 2), _Ws + (size_t)(bn + r0c) * K + _ko + c0e); \
        cp_async16(_sb + r1c * 80 + (c1e * 2), _Ws + (size_t)(bn + r1c) * K + _ko + c1e); \
        cp_commit();                                                               \
    } while (0)

    float acc[4][4][4];
#pragma unroll
    for (int i = 0; i < 4; ++i)
#pragma unroll
        for (int j = 0; j < 4; ++j)
#pragma unroll
            for (int q = 0; q < 4; ++q) acc[i][j][q] = 0.f;

    LDSTAGE(0);
    LDSTAGE(1);

    // fragment smem addressing (constant per thread)
    const uint32_t a_row = (lane & 15);
    const uint32_t a_kof = (lane >> 4) * 16;          // bytes: (lane>>4)*8 elems *2
    const uint32_t b_row = ((lane >> 4) & 1) * 8 + (lane & 7);
    const uint32_t b_kof = ((lane >> 3) & 1) * 16;    // bytes

    for (int s = 0; s < S; ++s) {
        if (s + 1 < S) cp_wait<1>(); else cp_wait<0>();
        __syncthreads();
        if (s + 2 < S) LDSTAGE(s + 2);

        uint32_t sa = sbase + (s % GSTAGES) * 2 * GTILEB;
        uint32_t sb = sa + GTILEB;
#pragma unroll
        for (int kk = 0; kk < 2; ++kk) {               // two K=16 chunks
            uint32_t af[4][4];
#pragma unroll
            for (int mi = 0; mi < 4; ++mi)
                ldsm4(af[mi][0], af[mi][1], af[mi][2], af[mi][3],
                      sa + (wm + mi * 16 + a_row) * 80 + kk * 32 + a_kof);
            uint32_t bfr[4][2];
#pragma unroll
            for (int pi = 0; pi < 2; ++pi) {
                uint32_t r0, r1, r2, r3;
                ldsm4(r0, r1, r2, r3,
                      sb + (wn + pi * 16 + b_row) * 80 + kk * 32 + b_kof);
                bfr[2 * pi][0] = r0; bfr[2 * pi][1] = r1;
                bfr[2 * pi + 1][0] = r2; bfr[2 * pi + 1][1] = r3;
            }
#pragma unroll
            for (int mi = 0; mi < 4; ++mi)
#pragma unroll
                for (int ni = 0; ni < 4; ++ni)
                    mma_bf16(acc[mi][ni], af[mi], bfr[ni]);
        }
        __syncthreads();
    }
#undef LDSTAGE

    // ---- epilogue ----
    const int erow = bm + wm + (lane >> 2);
    const int ecol = bn + wn + (lane & 3) * 2;
#pragma unroll
    for (int mi = 0; mi < 4; ++mi) {
#pragma unroll
        for (int ni = 0; ni < 4; ++ni) {
            int col = ecol + ni * 8;
            float b0 = 0.f, b1 = 0.f;
            if (EPI != 3) { b0 = bias[col]; b1 = bias[col + 1]; }
#pragma unroll
            for (int h = 0; h < 2; ++h) {              // h=0: row, h=1: row+8
                int row = erow + mi * 16 + h * 8;
                float v0 = acc[mi][ni][2 * h]     + b0;
                float v1 = acc[mi][ni][2 * h + 1] + b1;
                if (EPI == 1) {
                    v0 = gelu_exact(v0); v1 = gelu_exact(v1);
                    bf16 h0, l0, h1, l1;
                    split2(v0, h0, l0); split2(v1, h1, l1);
                    *(uint32_t*)&Chi[(size_t)row * N + col] = bf2pack(__bfloat162float(h0), __bfloat162float(h1));
                    *(uint32_t*)&Clo[(size_t)row * N + col] = bf2pack(__bfloat162float(l0), __bfloat162float(l1));
                } else {
                    if (EPI == 2) {
                        v0 += res[(size_t)row * N + col];
                        v1 += res[(size_t)row * N + col + 1];
                    }
                    float2 o2 = make_float2(v0, v1);
                    *(float2*)&C[(size_t)row * N + col] = o2;
                }
            }
        }
    }
}

// ---------------- fused causal attention (64-row Q tiles) ------------------------
#define ASTR 68
#define ATT_SMEM (4 * 64 * ASTR * 4)

__global__ void __launch_bounds__(256, 2)
attn_kernel(const float* __restrict__ qkv,
            bf16* __restrict__ ohi, bf16* __restrict__ olo)
{
    extern __shared__ float sm[];
    float* Qs = sm;
    float* Ks = Qs + 64 * ASTR;
    float* Vs = Ks + 64 * ASTR;
    float* Ps = Vs + 64 * ASTR;

    const int tid = threadIdx.x;
    const int bh  = blockIdx.y;
    const int b   = bh >> 4;
    const int hh  = bh & 15;
    const int q0  = blockIdx.x * 64;
    const int tx  = tid & 7;
    const int ty  = tid >> 3;
    const int r0  = ty * 2;
    const int c0  = tx * 8;

    const float* qbase = qkv + ((size_t)(b * TT + q0)) * (3 * DD) + hh * HD;
#pragma unroll
    for (int l = 0; l < 4; ++l) {
        int f = tid + l * 256;
        int r = f >> 4;
        int c = (f & 15) << 2;
        *(float4*)&Qs[r * ASTR + c] = *(const float4*)(qbase + (size_t)r * (3 * DD) + c);
    }

    float m[2], lsum[2], O[2][8];
#pragma unroll
    for (int i = 0; i < 2; ++i) {
        m[i] = -1e30f; lsum[i] = 0.f;
#pragma unroll
        for (int j = 0; j < 8; ++j) O[i][j] = 0.f;
    }

    const int ntiles = blockIdx.x + 1;
    for (int t = 0; t < ntiles; ++t) {
        const int j0 = t * 64;
        __syncthreads();
        const float* kbase = qkv + ((size_t)(b * TT + j0)) * (3 * DD) + DD + hh * HD;
        const float* vbase = kbase + DD;
#pragma unroll
        for (int l = 0; l < 4; ++l) {
            int f = tid + l * 256;
            int r = f >> 4;
            int c = (f & 15) << 2;
            *(float4*)&Ks[r * ASTR + c] = *(const float4*)(kbase + (size_t)r * (3 * DD) + c);
            *(float4*)&Vs[r * ASTR + c] = *(const float4*)(vbase + (size_t)r * (3 * DD) + c);
        }
        __syncthreads();

        float s[2][8] = {};
#pragma unroll
        for (int k4 = 0; k4 < 16; ++k4) {
            float4 qv[2];
#pragma unroll
            for (int i = 0; i < 2; ++i)
                qv[i] = *(const float4*)&Qs[(r0 + i) * ASTR + k4 * 4];
#pragma unroll
            for (int j = 0; j < 8; ++j) {
                float4 kv = *(const float4*)&Ks[(c0 + j) * ASTR + k4 * 4];
#pragma unroll
                for (int i = 0; i < 2; ++i)
                    s[i][j] += qv[i].x * kv.x + qv[i].y * kv.y
                             + qv[i].z * kv.z + qv[i].w * kv.w;
            }
        }

        const bool needmask = (j0 + 63 > q0);
#pragma unroll
        for (int i = 0; i < 2; ++i)
#pragma unroll
            for (int j = 0; j < 8; ++j) {
                float v = s[i][j] * 0.125f;
                if (needmask && (j0 + c0 + j > q0 + r0 + i)) v = -1e30f;
                s[i][j] = v;
            }

        float tm[2];
#pragma unroll
        for (int i = 0; i < 2; ++i) {
            float mx = s[i][0];
#pragma unroll
            for (int j = 1; j < 8; ++j) mx = fmaxf(mx, s[i][j]);
            tm[i] = mx;
        }
#pragma unroll
        for (int o = 1; o < 8; o <<= 1)
#pragma unroll
            for (int i = 0; i < 2; ++i)
                tm[i] = fmaxf(tm[i], __shfl_xor_sync(0xffffffffu, tm[i], o));

        float corr[2], ts[2];
#pragma unroll
        for (int i = 0; i < 2; ++i) {
            float mn = fmaxf(m[i], tm[i]);
            corr[i] = expf(m[i] - mn);
            m[i] = mn;
            ts[i] = 0.f;
#pragma unroll
            for (int j = 0; j < 8; ++j) {
                float p = expf(s[i][j] - mn);
                s[i][j] = p;
                ts[i] += p;
            }
        }
#pragma unroll
        for (int o = 1; o < 8; o <<= 1)
#pragma unroll
            for (int i = 0; i < 2; ++i)
                ts[i] += __shfl_xor_sync(0xffffffffu, ts[i], o);
#pragma unroll
        for (int i = 0; i < 2; ++i) {
            lsum[i] = lsum[i] * corr[i] + ts[i];
#pragma unroll
            for (int j = 0; j < 8; ++j) O[i][j] *= corr[i];
        }

#pragma unroll
        for (int i = 0; i < 2; ++i) {
            *(float4*)&Ps[(r0 + i) * ASTR + c0]     = make_float4(s[i][0], s[i][1], s[i][2], s[i][3]);
            *(float4*)&Ps[(r0 + i) * ASTR + c0 + 4] = make_float4(s[i][4], s[i][5], s[i][6], s[i][7]);
        }
        __syncthreads();

#pragma unroll
        for (int k4 = 0; k4 < 16; ++k4) {
            float p[2][4];
#pragma unroll
            for (int i = 0; i < 2; ++i) {
                float4 pv = *(const float4*)&Ps[(r0 + i) * ASTR + k4 * 4];
                p[i][0] = pv.x; p[i][1] = pv.y; p[i][2] = pv.z; p[i][3] = pv.w;
            }
#pragma unroll
            for (int u = 0; u < 4; ++u) {
                int kv = k4 * 4 + u;
                float4 va = *(const float4*)&Vs[kv * ASTR + c0];
                float4 vb = *(const float4*)&Vs[kv * ASTR + c0 + 4];
#pragma unroll
                for (int i = 0; i < 2; ++i) {
                    float pi = p[i][u];
                    O[i][0] += pi * va.x; O[i][1] += pi * va.y;
                    O[i][2] += pi * va.z; O[i][3] += pi * va.w;
                    O[i][4] += pi * vb.x; O[i][5] += pi * vb.y;
                    O[i][6] += pi * vb.z; O[i][7] += pi * vb.w;
                }
            }
        }
    }

    // write normalized O split into bf16 hi/lo
#pragma unroll
    for (int i = 0; i < 2; ++i) {
        float inv = 1.f / lsum[i];
        int qg = q0 + r0 + i;
        size_t off = ((size_t)(b * TT + qg)) * DD + hh * HD + c0;
        float v[8];
#pragma unroll
        for (int j = 0; j < 8; ++j) v[j] = O[i][j] * inv;
        uint4 hp, lp;
        bf16 h0, l0, h1, l1;
        split2(v[0], h0, l0); split2(v[1], h1, l1);
        hp.x = bf2pack(__bfloat162float(h0), __bfloat162float(h1));
        lp.x = bf2pack(__bfloat162float(l0), __bfloat162float(l1));
        split2(v[2], h0, l0); split2(v[3], h1, l1);
        hp.y = bf2pack(__bfloat162float(h0), __bfloat162float(h1));
        lp.y = bf2pack(__bfloat162float(l0), __bfloat162float(l1));
        split2(v[4], h0, l0); split2(v[5], h1, l1);
        hp.z = bf2pack(__bfloat162float(h0), __bfloat162float(h1));
        lp.z = bf2pack(__bfloat162float(l0), __bfloat162float(l1));
        split2(v[6], h0, l0); split2(v[7], h1, l1);
        hp.w = bf2pack(__bfloat162float(h0), __bfloat162float(h1));
        lp.w = bf2pack(__bfloat162float(l0), __bfloat162float(l1));
        *(uint4*)&ohi[off] = hp;
        *(uint4*)&olo[off] = lp;
    }
}

// ---------------- launch ---------------------------------------------------------
extern "C" void kernel_launch(void* const* d_in, const int* in_sizes, int n_in,
                              void* d_out, int out_size)
{
    const int*   idx     = (const int*)  d_in[0];
    const float* tok_emb = (const float*)d_in[1];
    const float* ln1_s   = (const float*)d_in[2];
    const float* ln1_b   = (const float*)d_in[3];
    const float* qkv_w   = (const float*)d_in[4];
    const float* qkv_b   = (const float*)d_in[5];
    const float* out_w   = (const float*)d_in[6];
    const float* out_b   = (const float*)d_in[7];
    const float* ln2_s   = (const float*)d_in[8];
    const float* ln2_b   = (const float*)d_in[9];
    const float* mlp_w1  = (const float*)d_in[10];
    const float* mlp_b1  = (const float*)d_in[11];
    const float* mlp_w2  = (const float*)d_in[12];
    const float* mlp_b2  = (const float*)d_in[13];
    const float* lnf_s   = (const float*)d_in[14];
    const float* lnf_b   = (const float*)d_in[15];
    const float* head_w  = (const float*)d_in[16];
    float* logits = (float*)d_out;

    float *x, *qkv;
    bf16 *ahi, *alo, *m1hi, *m1lo, *wh, *wl;
    cudaGetSymbolAddress((void**)&x,    g_x);
    cudaGetSymbolAddress((void**)&qkv,  g_qkv);
    cudaGetSymbolAddress((void**)&ahi,  g_ahi);
    cudaGetSymbolAddress((void**)&alo,  g_alo);
    cudaGetSymbolAddress((void**)&m1hi, g_m1hi);
    cudaGetSymbolAddress((void**)&m1lo, g_m1lo);
    cudaGetSymbolAddress((void**)&wh,   g_wh);
    cudaGetSymbolAddress((void**)&wl,   g_wl);

    cudaFuncSetAttribute(gemm_mma<0>, cudaFuncAttributeMaxDynamicSharedMemorySize, GSMEM);
    cudaFuncSetAttribute(gemm_mma<1>, cudaFuncAttributeMaxDynamicSharedMemorySize, GSMEM);
    cudaFuncSetAttribute(gemm_mma<2>, cudaFuncAttributeMaxDynamicSharedMemorySize, GSMEM);
    cudaFuncSetAttribute(gemm_mma<3>, cudaFuncAttributeMaxDynamicSharedMemorySize, GSMEM);
    cudaFuncSetAttribute(attn_kernel, cudaFuncAttributeMaxDynamicSharedMemorySize, ATT_SMEM);

    // ---- weight conversion (transpose + bf16 split), per launch ----
    for (int l = 0; l < LL; ++l) {
        size_t base = (size_t)l * LW;
        wconv_kernel<<<dim3(3*DD/32, DD/32), dim3(32,8)>>>(
            qkv_w + (size_t)l*DD*3*DD, wh + base, wl + base, DD, 3*DD);
        wconv_kernel<<<dim3(DD/32, DD/32), dim3(32,8)>>>(
            out_w + (size_t)l*DD*DD, wh + base + OFF_OUT, wl + base + OFF_OUT, DD, DD);
        wconv_kernel<<<dim3(FF_/32, DD/32), dim3(32,8)>>>(
            mlp_w1 + (size_t)l*DD*FF_, wh + base + OFF_M1, wl + base + OFF_M1, DD, FF_);
        wconv_kernel<<<dim3(DD/32, FF_/32), dim3(32,8)>>>(
            mlp_w2 + (size_t)l*FF_*DD, wh + base + OFF_M2, wl + base + OFF_M2, FF_, DD);
    }
    wconv_kernel<<<dim3(VV/32, DD/32), dim3(32,8)>>>(
        head_w, wh + OFF_HD, wl + OFF_HD, DD, VV);

    embed_kernel<<<MM, 256>>>(idx, tok_emb, x);

    for (int l = 0; l < LL; ++l) {
        size_t base = (size_t)l * LW;

        ln_kernel<<<MM, 256>>>(x, ln1_s + (size_t)l*DD, ln1_b + (size_t)l*DD, ahi, alo);

        gemm_mma<0><<<dim3(3*DD/128, MM/128), 256, GSMEM>>>(
            ahi, alo, wh + base, wl + base,
            qkv_b + (size_t)l*3*DD, nullptr, qkv, nullptr, nullptr, 3*DD, DD);

        attn_kernel<<<dim3(TT/64, BB*HH), 256, ATT_SMEM>>>(qkv, ahi, alo);

        gemm_mma<2><<<dim3(DD/128, MM/128), 256, GSMEM>>>(
            ahi, alo, wh + base + OFF_OUT, wl + base + OFF_OUT,
            out_b + (size_t)l*DD, x, x, nullptr, nullptr, DD, DD);

        ln_kernel<<<MM, 256>>>(x, ln2_s + (size_t)l*DD, ln2_b + (size_t)l*DD, ahi, alo);

        gemm_mma<1><<<dim3(FF_/128, MM/128), 256, GSMEM>>>(
            ahi, alo, wh + base + OFF_M1, wl + base + OFF_M1,
            mlp_b1 + (size_t)l*FF_, nullptr, nullptr, m1hi, m1lo, FF_, DD);

        gemm_mma<2><<<dim3(DD/128, MM/128), 256, GSMEM>>>(
            m1hi, m1lo, wh + base + OFF_M2, wl + base + OFF_M2,
            mlp_b2 + (size_t)l*DD, x, x, nullptr, nullptr, DD, FF_);
    }

    ln_kernel<<<MM, 256>>>(x, lnf_s, lnf_b, ahi, alo);

    gemm_mma<3><<<dim3(VV/128, MM/128), 256, GSMEM>>>(
        ahi, alo, wh + OFF_HD, wl + OFF_HD,
        nullptr, nullptr, logits, nullptr, nullptr, VV, DD);
}

// round 4
// speedup vs baseline: 1.4921x; 1.0970x over previous
#include <cuda_runtime.h>
#include <cuda_bf16.h>
#include <math.h>
#include <stdint.h>

// Problem constants
#define BB 2
#define TT 1024
#define DD 1024
#define HH 16
#define HD 64
#define FF_ 4096
#define LL 8
#define VV 32000
#define MM (BB*TT)   // 2048

typedef __nv_bfloat16 bf16;

// ---------------- scratch (static device globals; allocation-free) -------------
__device__ float g_x   [MM * DD];
__device__ float g_qkv [MM * 3 * DD];
__device__ bf16  g_ahi [MM * DD];
__device__ bf16  g_alo [MM * DD];
__device__ bf16  g_m1hi[MM * FF_];
__device__ bf16  g_m1lo[MM * FF_];

// transposed + bf16-split weights, [N,K] row-major per matrix
#define LW      12582912ULL
#define OFF_OUT 3145728ULL
#define OFF_M1  4194304ULL
#define OFF_M2  8388608ULL
#define OFF_HD  100663296ULL
#define WTOT    133431296ULL
__device__ bf16 g_wh[WTOT];
__device__ bf16 g_wl[WTOT];

// ---------------- helpers -------------------------------------------------------
__device__ __forceinline__ uint32_t smem_u32(const void* p) {
    uint32_t a;
    asm("{ .reg .u64 t; cvta.to.shared.u64 t, %1; cvt.u32.u64 %0, t; }" : "=r"(a) : "l"(p));
    return a;
}
__device__ __forceinline__ void cp_async16(uint32_t saddr, const void* gaddr) {
    asm volatile("cp.async.cg.shared.global [%0], [%1], 16;" :: "r"(saddr), "l"(gaddr));
}
__device__ __forceinline__ void cp_commit() { asm volatile("cp.async.commit_group;"); }
template<int N>
__device__ __forceinline__ void cp_wait() { asm volatile("cp.async.wait_group %0;" :: "n"(N)); }

__device__ __forceinline__ void ldsm4(uint32_t& r0, uint32_t& r1, uint32_t& r2, uint32_t& r3,
                                      uint32_t addr) {
    asm volatile("ldmatrix.sync.aligned.m8n8.x4.shared.b16 {%0,%1,%2,%3}, [%4];"
                 : "=r"(r0), "=r"(r1), "=r"(r2), "=r"(r3) : "r"(addr));
}
__device__ __forceinline__ void mma_bf16(float* d, const uint32_t* a, const uint32_t* b) {
    asm volatile(
        "mma.sync.aligned.m16n8k16.row.col.f32.bf16.bf16.f32 "
        "{%0,%1,%2,%3}, {%4,%5,%6,%7}, {%8,%9}, {%0,%1,%2,%3};"
        : "+f"(d[0]), "+f"(d[1]), "+f"(d[2]), "+f"(d[3])
        : "r"(a[0]), "r"(a[1]), "r"(a[2]), "r"(a[3]), "r"(b[0]), "r"(b[1]));
}
__device__ __forceinline__ uint32_t bf2pack(float a, float b) {
    __nv_bfloat162 t = __floats2bfloat162_rn(a, b);
    return *(uint32_t*)&t;
}
__device__ __forceinline__ void split2(float v, bf16& h, bf16& l) {
    h = __float2bfloat16_rn(v);
    l = __float2bfloat16_rn(v - __bfloat162float(h));
}
__device__ __forceinline__ float gelu_exact(float x) {
    return 0.5f * x * (1.f + erff(x * 0.7071067811865475f));
}

// ---------------- embed ---------------------------------------------------------
__global__ void embed_kernel(const int* __restrict__ idx,
                             const float* __restrict__ emb,
                             float* __restrict__ x)
{
    int bt  = blockIdx.x;
    int t   = bt & (TT - 1);
    int tok = idx[bt];
    int c0  = threadIdx.x * 4;
    const float kfac = -9.210340371976184f / (float)DD;
#pragma unroll
    for (int u = 0; u < 4; ++u) {
        int c  = c0 + u;
        int i2 = c & ~1;
        float freq = expf((float)i2 * kfac);
        float ang  = (float)t * freq;
        float pe   = (c & 1) ? cosf(ang) : sinf(ang);
        x[(size_t)bt * DD + c] = emb[(size_t)tok * DD + c] + pe;
    }
}

// ---------------- layernorm -> bf16 hi/lo pair -----------------------------------
__global__ void ln_kernel(const float* __restrict__ x,
                          const float* __restrict__ s,
                          const float* __restrict__ b,
                          bf16* __restrict__ yhi,
                          bf16* __restrict__ ylo)
{
    int row = blockIdx.x, tid = threadIdx.x;
    const float4* xr = (const float4*)(x + (size_t)row * DD);
    float4 v = xr[tid];
    float sum = v.x + v.y + v.z + v.w;
    float sq  = v.x*v.x + v.y*v.y + v.z*v.z + v.w*v.w;
#pragma unroll
    for (int o = 16; o > 0; o >>= 1) {
        sum += __shfl_xor_sync(0xffffffffu, sum, o);
        sq  += __shfl_xor_sync(0xffffffffu, sq,  o);
    }
    __shared__ float ssum[8], ssq[8];
    int warp = tid >> 5, lane = tid & 31;
    if (lane == 0) { ssum[warp] = sum; ssq[warp] = sq; }
    __syncthreads();
    if (tid < 32) {
        float a = (tid < 8) ? ssum[tid] : 0.f;
        float c = (tid < 8) ? ssq [tid] : 0.f;
#pragma unroll
        for (int o = 4; o > 0; o >>= 1) {
            a += __shfl_xor_sync(0xffffffffu, a, o);
            c += __shfl_xor_sync(0xffffffffu, c, o);
        }
        if (tid == 0) { ssum[0] = a; ssq[0] = c; }
    }
    __syncthreads();
    float mean = ssum[0] * (1.f / DD);
    float var  = ssq[0]  * (1.f / DD) - mean * mean;
    float rstd = rsqrtf(var + 1e-5f);
    float4 sv = ((const float4*)s)[tid];
    float4 bv = ((const float4*)b)[tid];
    float o0 = (v.x - mean) * rstd * sv.x + bv.x;
    float o1 = (v.y - mean) * rstd * sv.y + bv.y;
    float o2 = (v.z - mean) * rstd * sv.z + bv.z;
    float o3 = (v.w - mean) * rstd * sv.w + bv.w;
    bf16 h0,l0,h1,l1,h2,l2,h3,l3;
    split2(o0,h0,l0); split2(o1,h1,l1); split2(o2,h2,l2); split2(o3,h3,l3);
    uint2 hp, lp;
    hp.x = bf2pack(__bfloat162float(h0), __bfloat162float(h1));
    hp.y = bf2pack(__bfloat162float(h2), __bfloat162float(h3));
    lp.x = bf2pack(__bfloat162float(l0), __bfloat162float(l1));
    lp.y = bf2pack(__bfloat162float(l2), __bfloat162float(l3));
    *(uint2*)&yhi[(size_t)row * DD + tid * 4] = hp;
    *(uint2*)&ylo[(size_t)row * DD + tid * 4] = lp;
}

// ---------------- weight transpose + bf16 split: W[K,N] -> {hi,lo}[N,K] ----------
__global__ void wconv_kernel(const float* __restrict__ W,
                             bf16* __restrict__ Thi, bf16* __restrict__ Tlo,
                             int K, int N)
{
    __shared__ float tile[32][33];
    int n0 = blockIdx.x * 32, k0 = blockIdx.y * 32;
    int tx = threadIdx.x, ty = threadIdx.y;
#pragma unroll
    for (int j = 0; j < 32; j += 8)
        tile[ty + j][tx] = W[(size_t)(k0 + ty + j) * N + n0 + tx];
    __syncthreads();
#pragma unroll
    for (int j = 0; j < 32; j += 8) {
        float v = tile[tx][ty + j];
        bf16 hi, lo;
        split2(v, hi, lo);
        size_t o = (size_t)(n0 + ty + j) * K + k0 + tx;
        Thi[o] = hi; Tlo[o] = lo;
    }
}

// ---------------- bf16x3 GEMM v2: 4 warps, 64x64 warp tile, 4-stage pipe ---------
// C[M,N] = A[M,K] @ W[N,K]^T over 3 segments (Ahi*Whi, Ahi*Wlo, Alo*Whi)
// EPI: 0 = +bias -> C(f32) ; 1 = +bias,GELU -> split(Chi,Clo) ; 2 = +bias+res -> C ; 3 = plain
#define GBK 32
#define GSTAGES 4
#define GST_BYTES 16384                 // per stage: A 8KB + B 8KB
#define GSMEM (GSTAGES * GST_BYTES)     // 64 KB

template<int EPI>
__global__ void __launch_bounds__(128, 2)
gemm_mma(const bf16* __restrict__ Ahi, const bf16* __restrict__ Alo,
         const bf16* __restrict__ Whi, const bf16* __restrict__ Wlo,
         const float* __restrict__ bias, const float* __restrict__ res,
         float* __restrict__ C, bf16* __restrict__ Chi, bf16* __restrict__ Clo,
         int N, int K)
{
    extern __shared__ char smraw[];
    const uint32_t sbase = smem_u32(smraw);

    const int tid  = threadIdx.x;
    const int wid  = tid >> 5, lane = tid & 31;
    const int bm   = blockIdx.y * 128, bn = blockIdx.x * 128;
    const int wm   = (wid >> 1) * 64;      // warp M offset (0/64)
    const int wn   = (wid & 1) * 64;       // warp N offset (0/64)

    const int S = (3 * K) / GBK;

    // per-thread load ids: 4 chunks for A, 4 for B; chunk id = tid + i*128
    // row = id>>2 (0..127), logical chunk lc = id&3, phys = lc ^ ((row>>1)&3)
#define LDSTAGE(sidx)                                                                  \
    do {                                                                               \
        int _kg = (sidx) * GBK;                                                        \
        int _seg = _kg / K, _ko = _kg - _seg * K;                                      \
        const bf16* _As = (_seg < 2) ? Ahi : Alo;                                      \
        const bf16* _Ws = (_seg == 1) ? Wlo : Whi;                                     \
        uint32_t _st = sbase + ((sidx) & 3) * GST_BYTES;                               \
        _Pragma("unroll")                                                              \
        for (int _i = 0; _i < 4; ++_i) {                                               \
            int _id = tid + _i * 128;                                                  \
            int _r = _id >> 2, _lc = _id & 3;                                          \
            int _ph = _lc ^ ((_r >> 1) & 3);                                           \
            cp_async16(_st + _r * 64 + (_ph << 4),                                     \
                       _As + (size_t)(bm + _r) * K + _ko + _lc * 8);                   \
            cp_async16(_st + 8192 + _r * 64 + (_ph << 4),                              \
                       _Ws + (size_t)(bn + _r) * K + _ko + _lc * 8);                   \
        }                                                                              \
        cp_commit();                                                                   \
    } while (0)

    float acc[4][8][4];
#pragma unroll
    for (int i = 0; i < 4; ++i)
#pragma unroll
        for (int j = 0; j < 8; ++j)
#pragma unroll
            for (int q = 0; q < 4; ++q) acc[i][j][q] = 0.f;

    LDSTAGE(0);
    LDSTAGE(1);

    // ldsm row constants
    int arow[4], asw[4];
#pragma unroll
    for (int mi = 0; mi < 4; ++mi) {
        int r = wm + mi * 16 + (lane & 15);
        arow[mi] = r * 64;
        asw[mi]  = (r >> 1) & 3;
    }
    int brow[4], bsw[4];
#pragma unroll
    for (int pi = 0; pi < 4; ++pi) {
        int r = wn + pi * 16 + ((lane >> 4) & 1) * 8 + (lane & 7);
        brow[pi] = r * 64;
        bsw[pi]  = (r >> 1) & 3;
    }
    const int alc0 = (lane >> 4) & 1;    // A chunk low bit
    const int blc0 = (lane >> 3) & 1;    // B chunk low bit

    for (int s = 0; s < S; ++s) {
        cp_wait<1>();
        __syncthreads();
        if (s + 2 < S) LDSTAGE(s + 2);

        const uint32_t sa = sbase + (s & 3) * GST_BYTES;
        const uint32_t sb = sa + 8192;
#pragma unroll
        for (int kk = 0; kk < 2; ++kk) {
            uint32_t af[4][4];
#pragma unroll
            for (int mi = 0; mi < 4; ++mi) {
                int lc = kk * 2 + alc0;
                ldsm4(af[mi][0], af[mi][1], af[mi][2], af[mi][3],
                      sa + arow[mi] + ((lc ^ asw[mi]) << 4));
            }
            uint32_t bfr[8][2];
#pragma unroll
            for (int pi = 0; pi < 4; ++pi) {
                int lc = kk * 2 + blc0;
                uint32_t r0, r1, r2, r3;
                ldsm4(r0, r1, r2, r3, sb + brow[pi] + ((lc ^ bsw[pi]) << 4));
                bfr[2 * pi][0] = r0;     bfr[2 * pi][1] = r1;
                bfr[2 * pi + 1][0] = r2; bfr[2 * pi + 1][1] = r3;
            }
#pragma unroll
            for (int mi = 0; mi < 4; ++mi)
#pragma unroll
                for (int ni = 0; ni < 8; ++ni)
                    mma_bf16(acc[mi][ni], af[mi], bfr[ni]);
        }
    }
#undef LDSTAGE

    // ---- epilogue: each warp writes its 64x64 tile ----
    const int r_base = bm + wm + (lane >> 2);
    const int c_base = bn + wn + (lane & 3) * 2;
#pragma unroll
    for (int mi = 0; mi < 4; ++mi) {
#pragma unroll
        for (int ni = 0; ni < 8; ++ni) {
            int col = c_base + ni * 8;
            float b0 = 0.f, b1 = 0.f;
            if (EPI != 3) { b0 = bias[col]; b1 = bias[col + 1]; }
#pragma unroll
            for (int h = 0; h < 2; ++h) {
                int row = r_base + mi * 16 + h * 8;
                float v0 = acc[mi][ni][2 * h]     + b0;
                float v1 = acc[mi][ni][2 * h + 1] + b1;
                if (EPI == 1) {
                    v0 = gelu_exact(v0); v1 = gelu_exact(v1);
                    bf16 h0, l0, h1, l1;
                    split2(v0, h0, l0); split2(v1, h1, l1);
                    *(uint32_t*)&Chi[(size_t)row * N + col] = bf2pack(__bfloat162float(h0), __bfloat162float(h1));
                    *(uint32_t*)&Clo[(size_t)row * N + col] = bf2pack(__bfloat162float(l0), __bfloat162float(l1));
                } else {
                    if (EPI == 2) {
                        v0 += res[(size_t)row * N + col];
                        v1 += res[(size_t)row * N + col + 1];
                    }
                    *(float2*)&C[(size_t)row * N + col] = make_float2(v0, v1);
                }
            }
        }
    }
}

// ---------------- fused causal attention (64-row Q tiles) ------------------------
#define ASTR 68
#define ATT_SMEM (4 * 64 * ASTR * 4)

__global__ void __launch_bounds__(256, 2)
attn_kernel(const float* __restrict__ qkv,
            bf16* __restrict__ ohi, bf16* __restrict__ olo)
{
    extern __shared__ float sm[];
    float* Qs = sm;
    float* Ks = Qs + 64 * ASTR;
    float* Vs = Ks + 64 * ASTR;
    float* Ps = Vs + 64 * ASTR;

    const int tid = threadIdx.x;
    const int bh  = blockIdx.y;
    const int b   = bh >> 4;
    const int hh  = bh & 15;
    const int q0  = blockIdx.x * 64;
    const int tx  = tid & 7;
    const int ty  = tid >> 3;
    const int r0  = ty * 2;
    const int c0  = tx * 8;

    const float* qbase = qkv + ((size_t)(b * TT + q0)) * (3 * DD) + hh * HD;
#pragma unroll
    for (int l = 0; l < 4; ++l) {
        int f = tid + l * 256;
        int r = f >> 4;
        int c = (f & 15) << 2;
        *(float4*)&Qs[r * ASTR + c] = *(const float4*)(qbase + (size_t)r * (3 * DD) + c);
    }

    float m[2], lsum[2], O[2][8];
#pragma unroll
    for (int i = 0; i < 2; ++i) {
        m[i] = -1e30f; lsum[i] = 0.f;
#pragma unroll
        for (int j = 0; j < 8; ++j) O[i][j] = 0.f;
    }

    const int ntiles = blockIdx.x + 1;
    for (int t = 0; t < ntiles; ++t) {
        const int j0 = t * 64;
        __syncthreads();
        const float* kbase = qkv + ((size_t)(b * TT + j0)) * (3 * DD) + DD + hh * HD;
        const float* vbase = kbase + DD;
#pragma unroll
        for (int l = 0; l < 4; ++l) {
            int f = tid + l * 256;
            int r = f >> 4;
            int c = (f & 15) << 2;
            *(float4*)&Ks[r * ASTR + c] = *(const float4*)(kbase + (size_t)r * (3 * DD) + c);
            *(float4*)&Vs[r * ASTR + c] = *(const float4*)(vbase + (size_t)r * (3 * DD) + c);
        }
        __syncthreads();

        float s[2][8] = {};
#pragma unroll
        for (int k4 = 0; k4 < 16; ++k4) {
            float4 qv[2];
#pragma unroll
            for (int i = 0; i < 2; ++i)
                qv[i] = *(const float4*)&Qs[(r0 + i) * ASTR + k4 * 4];
#pragma unroll
            for (int j = 0; j < 8; ++j) {
                float4 kv = *(const float4*)&Ks[(c0 + j) * ASTR + k4 * 4];
#pragma unroll
                for (int i = 0; i < 2; ++i)
                    s[i][j] += qv[i].x * kv.x + qv[i].y * kv.y
                             + qv[i].z * kv.z + qv[i].w * kv.w;
            }
        }

        const bool needmask = (j0 + 63 > q0);
#pragma unroll
        for (int i = 0; i < 2; ++i)
#pragma unroll
            for (int j = 0; j < 8; ++j) {
                float v = s[i][j] * 0.125f;
                if (needmask && (j0 + c0 + j > q0 + r0 + i)) v = -1e30f;
                s[i][j] = v;
            }

        float tm[2];
#pragma unroll
        for (int i = 0; i < 2; ++i) {
            float mx = s[i][0];
#pragma unroll
            for (int j = 1; j < 8; ++j) mx = fmaxf(mx, s[i][j]);
            tm[i] = mx;
        }
#pragma unroll
        for (int o = 1; o < 8; o <<= 1)
#pragma unroll
            for (int i = 0; i < 2; ++i)
                tm[i] = fmaxf(tm[i], __shfl_xor_sync(0xffffffffu, tm[i], o));

        float corr[2], ts[2];
#pragma unroll
        for (int i = 0; i < 2; ++i) {
            float mn = fmaxf(m[i], tm[i]);
            corr[i] = expf(m[i] - mn);
            m[i] = mn;
            ts[i] = 0.f;
#pragma unroll
            for (int j = 0; j < 8; ++j) {
                float p = expf(s[i][j] - mn);
                s[i][j] = p;
                ts[i] += p;
            }
        }
#pragma unroll
        for (int o = 1; o < 8; o <<= 1)
#pragma unroll
            for (int i = 0; i < 2; ++i)
                ts[i] += __shfl_xor_sync(0xffffffffu, ts[i], o);
#pragma unroll
        for (int i = 0; i < 2; ++i) {
            lsum[i] = lsum[i] * corr[i] + ts[i];
#pragma unroll
            for (int j = 0; j < 8; ++j) O[i][j] *= corr[i];
        }

#pragma unroll
        for (int i = 0; i < 2; ++i) {
            *(float4*)&Ps[(r0 + i) * ASTR + c0]     = make_float4(s[i][0], s[i][1], s[i][2], s[i][3]);
            *(float4*)&Ps[(r0 + i) * ASTR + c0 + 4] = make_float4(s[i][4], s[i][5], s[i][6], s[i][7]);
        }
        __syncthreads();

#pragma unroll
        for (int k4 = 0; k4 < 16; ++k4) {
            float p[2][4];
#pragma unroll
            for (int i = 0; i < 2; ++i) {
                float4 pv = *(const float4*)&Ps[(r0 + i) * ASTR + k4 * 4];
                p[i][0] = pv.x; p[i][1] = pv.y; p[i][2] = pv.z; p[i][3] = pv.w;
            }
#pragma unroll
            for (int u = 0; u < 4; ++u) {
                int kv = k4 * 4 + u;
                float4 va = *(const float4*)&Vs[kv * ASTR + c0];
                float4 vb = *(const float4*)&Vs[kv * ASTR + c0 + 4];
#pragma unroll
                for (int i = 0; i < 2; ++i) {
                    float pi = p[i][u];
                    O[i][0] += pi * va.x; O[i][1] += pi * va.y;
                    O[i][2] += pi * va.z; O[i][3] += pi * va.w;
                    O[i][4] += pi * vb.x; O[i][5] += pi * vb.y;
                    O[i][6] += pi * vb.z; O[i][7] += pi * vb.w;
                }
            }
        }
    }

#pragma unroll
    for (int i = 0; i < 2; ++i) {
        float inv = 1.f / lsum[i];
        int qg = q0 + r0 + i;
        size_t off = ((size_t)(b * TT + qg)) * DD + hh * HD + c0;
        float v[8];
#pragma unroll
        for (int j = 0; j < 8; ++j) v[j] = O[i][j] * inv;
        uint4 hp, lp;
        bf16 h0, l0, h1, l1;
        split2(v[0], h0, l0); split2(v[1], h1, l1);
        hp.x = bf2pack(__bfloat162float(h0), __bfloat162float(h1));
        lp.x = bf2pack(__bfloat162float(l0), __bfloat162float(l1));
        split2(v[2], h0, l0); split2(v[3], h1, l1);
        hp.y = bf2pack(__bfloat162float(h0), __bfloat162float(h1));
        lp.y = bf2pack(__bfloat162float(l0), __bfloat162float(l1));
        split2(v[4], h0, l0); split2(v[5], h1, l1);
        hp.z = bf2pack(__bfloat162float(h0), __bfloat162float(h1));
        lp.z = bf2pack(__bfloat162float(l0), __bfloat162float(l1));
        split2(v[6], h0, l0); split2(v[7], h1, l1);
        hp.w = bf2pack(__bfloat162float(h0), __bfloat162float(h1));
        lp.w = bf2pack(__bfloat162float(l0), __bfloat162float(l1));
        *(uint4*)&ohi[off] = hp;
        *(uint4*)&olo[off] = lp;
    }
}

// ---------------- launch ---------------------------------------------------------
extern "C" void kernel_launch(void* const* d_in, const int* in_sizes, int n_in,
                              void* d_out, int out_size)
{
    const int*   idx     = (const int*)  d_in[0];
    const float* tok_emb = (const float*)d_in[1];
    const float* ln1_s   = (const float*)d_in[2];
    const float* ln1_b   = (const float*)d_in[3];
    const float* qkv_w   = (const float*)d_in[4];
    const float* qkv_b   = (const float*)d_in[5];
    const float* out_w   = (const float*)d_in[6];
    const float* out_b   = (const float*)d_in[7];
    const float* ln2_s   = (const float*)d_in[8];
    const float* ln2_b   = (const float*)d_in[9];
    const float* mlp_w1  = (const float*)d_in[10];
    const float* mlp_b1  = (const float*)d_in[11];
    const float* mlp_w2  = (const float*)d_in[12];
    const float* mlp_b2  = (const float*)d_in[13];
    const float* lnf_s   = (const float*)d_in[14];
    const float* lnf_b   = (const float*)d_in[15];
    const float* head_w  = (const float*)d_in[16];
    float* logits = (float*)d_out;

    float *x, *qkv;
    bf16 *ahi, *alo, *m1hi, *m1lo, *wh, *wl;
    cudaGetSymbolAddress((void**)&x,    g_x);
    cudaGetSymbolAddress((void**)&qkv,  g_qkv);
    cudaGetSymbolAddress((void**)&ahi,  g_ahi);
    cudaGetSymbolAddress((void**)&alo,  g_alo);
    cudaGetSymbolAddress((void**)&m1hi, g_m1hi);
    cudaGetSymbolAddress((void**)&m1lo, g_m1lo);
    cudaGetSymbolAddress((void**)&wh,   g_wh);
    cudaGetSymbolAddress((void**)&wl,   g_wl);

    cudaFuncSetAttribute(gemm_mma<0>, cudaFuncAttributeMaxDynamicSharedMemorySize, GSMEM);
    cudaFuncSetAttribute(gemm_mma<1>, cudaFuncAttributeMaxDynamicSharedMemorySize, GSMEM);
    cudaFuncSetAttribute(gemm_mma<2>, cudaFuncAttributeMaxDynamicSharedMemorySize, GSMEM);
    cudaFuncSetAttribute(gemm_mma<3>, cudaFuncAttributeMaxDynamicSharedMemorySize, GSMEM);
    cudaFuncSetAttribute(attn_kernel, cudaFuncAttributeMaxDynamicSharedMemorySize, ATT_SMEM);

    // ---- weight conversion (transpose + bf16 split), per launch ----
    for (int l = 0; l < LL; ++l) {
        size_t base = (size_t)l * LW;
        wconv_kernel<<<dim3(3*DD/32, DD/32), dim3(32,8)>>>(
            qkv_w + (size_t)l*DD*3*DD, wh + base, wl + base, DD, 3*DD);
        wconv_kernel<<<dim3(DD/32, DD/32), dim3(32,8)>>>(
            out_w + (size_t)l*DD*DD, wh + base + OFF_OUT, wl + base + OFF_OUT, DD, DD);
        wconv_kernel<<<dim3(FF_/32, DD/32), dim3(32,8)>>>(
            mlp_w1 + (size_t)l*DD*FF_, wh + base + OFF_M1, wl + base + OFF_M1, DD, FF_);
        wconv_kernel<<<dim3(DD/32, FF_/32), dim3(32,8)>>>(
            mlp_w2 + (size_t)l*FF_*DD, wh + base + OFF_M2, wl + base + OFF_M2, FF_, DD);
    }
    wconv_kernel<<<dim3(VV/32, DD/32), dim3(32,8)>>>(
        head_w, wh + OFF_HD, wl + OFF_HD, DD, VV);

    embed_kernel<<<MM, 256>>>(idx, tok_emb, x);

    for (int l = 0; l < LL; ++l) {
        size_t base = (size_t)l * LW;

        ln_kernel<<<MM, 256>>>(x, ln1_s + (size_t)l*DD, ln1_b + (size_t)l*DD, ahi, alo);

        gemm_mma<0><<<dim3(3*DD/128, MM/128), 128, GSMEM>>>(
            ahi, alo, wh + base, wl + base,
            qkv_b + (size_t)l*3*DD, nullptr, qkv, nullptr, nullptr, 3*DD, DD);

        attn_kernel<<<dim3(TT/64, BB*HH), 256, ATT_SMEM>>>(qkv, ahi, alo);

        gemm_mma<2><<<dim3(DD/128, MM/128), 128, GSMEM>>>(
            ahi, alo, wh + base + OFF_OUT, wl + base + OFF_OUT,
            out_b + (size_t)l*DD, x, x, nullptr, nullptr, DD, DD);

        ln_kernel<<<MM, 256>>>(x, ln2_s + (size_t)l*DD, ln2_b + (size_t)l*DD, ahi, alo);

        gemm_mma<1><<<dim3(FF_/128, MM/128), 128, GSMEM>>>(
            ahi, alo, wh + base + OFF_M1, wl + base + OFF_M1,
            mlp_b1 + (size_t)l*FF_, nullptr, nullptr, m1hi, m1lo, FF_, DD);

        gemm_mma<2><<<dim3(DD/128, MM/128), 128, GSMEM>>>(
            m1hi, m1lo, wh + base + OFF_M2, wl + base + OFF_M2,
            mlp_b2 + (size_t)l*DD, x, x, nullptr, nullptr, DD, FF_);
    }

    ln_kernel<<<MM, 256>>>(x, lnf_s, lnf_b, ahi, alo);

    gemm_mma<3><<<dim3(VV/128, MM/128), 128, GSMEM>>>(
        ahi, alo, wh + OFF_HD, wl + OFF_HD,
        nullptr, nullptr, logits, nullptr, nullptr, VV, DD);
}

// round 5
// speedup vs baseline: 1.6209x; 1.0863x over previous
#include <cuda_runtime.h>
#include <cuda_bf16.h>
#include <cuda_fp16.h>
#include <math.h>
#include <stdint.h>

// Problem constants
#define BB 2
#define TT 1024
#define DD 1024
#define HH 16
#define HD 64
#define FF_ 4096
#define LL 8
#define VV 32000
#define MM (BB*TT)   // 2048

typedef __nv_bfloat16 bf16;

// ---------------- scratch (static device globals; allocation-free) -------------
__device__ float g_x   [MM * DD];
__device__ float g_qkv [MM * 3 * DD];
__device__ bf16  g_ahi [MM * DD];
__device__ bf16  g_alo [MM * DD];
__device__ bf16  g_m1hi[MM * FF_];
__device__ bf16  g_m1lo[MM * FF_];

// transposed + split weights, [N,K] row-major per matrix (2-byte elems)
#define LW      12582912ULL
#define OFF_OUT 3145728ULL
#define OFF_M1  4194304ULL
#define OFF_M2  8388608ULL
#define OFF_HD  100663296ULL
#define WTOT    133431296ULL
__device__ uint16_t g_wh[WTOT];
__device__ uint16_t g_wl[WTOT];

// ---------------- helpers -------------------------------------------------------
__device__ __forceinline__ uint32_t smem_u32(const void* p) {
    uint32_t a;
    asm("{ .reg .u64 t; cvta.to.shared.u64 t, %1; cvt.u32.u64 %0, t; }" : "=r"(a) : "l"(p));
    return a;
}
__device__ __forceinline__ void cp_async16(uint32_t saddr, const void* gaddr) {
    asm volatile("cp.async.cg.shared.global [%0], [%1], 16;" :: "r"(saddr), "l"(gaddr));
}
__device__ __forceinline__ void cp_commit() { asm volatile("cp.async.commit_group;"); }
template<int N>
__device__ __forceinline__ void cp_wait() { asm volatile("cp.async.wait_group %0;" :: "n"(N)); }

__device__ __forceinline__ void ldsm4(uint32_t& r0, uint32_t& r1, uint32_t& r2, uint32_t& r3,
                                      uint32_t addr) {
    asm volatile("ldmatrix.sync.aligned.m8n8.x4.shared.b16 {%0,%1,%2,%3}, [%4];"
                 : "=r"(r0), "=r"(r1), "=r"(r2), "=r"(r3) : "r"(addr));
}
template<int F16>
__device__ __forceinline__ void mma_tc(float* d, const uint32_t* a, const uint32_t* b) {
    if (F16)
        asm volatile(
            "mma.sync.aligned.m16n8k16.row.col.f32.f16.f16.f32 "
            "{%0,%1,%2,%3}, {%4,%5,%6,%7}, {%8,%9}, {%0,%1,%2,%3};"
            : "+f"(d[0]), "+f"(d[1]), "+f"(d[2]), "+f"(d[3])
            : "r"(a[0]), "r"(a[1]), "r"(a[2]), "r"(a[3]), "r"(b[0]), "r"(b[1]));
    else
        asm volatile(
            "mma.sync.aligned.m16n8k16.row.col.f32.bf16.bf16.f32 "
            "{%0,%1,%2,%3}, {%4,%5,%6,%7}, {%8,%9}, {%0,%1,%2,%3};"
            : "+f"(d[0]), "+f"(d[1]), "+f"(d[2]), "+f"(d[3])
            : "r"(a[0]), "r"(a[1]), "r"(a[2]), "r"(a[3]), "r"(b[0]), "r"(b[1]));
}
__device__ __forceinline__ uint32_t bf2pack(float a, float b) {
    __nv_bfloat162 t = __floats2bfloat162_rn(a, b);
    return *(uint32_t*)&t;
}
__device__ __forceinline__ void split2(float v, bf16& h, bf16& l) {
    h = __float2bfloat16_rn(v);
    l = __float2bfloat16_rn(v - __bfloat162float(h));
}
__device__ __forceinline__ float gelu_exact(float x) {
    return 0.5f * x * (1.f + erff(x * 0.7071067811865475f));
}

// ---------------- embed ---------------------------------------------------------
__global__ void embed_kernel(const int* __restrict__ idx,
                             const float* __restrict__ emb,
                             float* __restrict__ x)
{
    int bt  = blockIdx.x;
    int t   = bt & (TT - 1);
    int tok = idx[bt];
    int c0  = threadIdx.x * 4;
    const float kfac = -9.210340371976184f / (float)DD;
#pragma unroll
    for (int u = 0; u < 4; ++u) {
        int c  = c0 + u;
        int i2 = c & ~1;
        float freq = expf((float)i2 * kfac);
        float ang  = (float)t * freq;
        float pe   = (c & 1) ? cosf(ang) : sinf(ang);
        x[(size_t)bt * DD + c] = emb[(size_t)tok * DD + c] + pe;
    }
}

// ---------------- layernorm core ------------------------------------------------
__device__ __forceinline__ void ln_stats(const float4& v, float& mean, float& rstd,
                                         float* ssum, float* ssq, int tid)
{
    float sum = v.x + v.y + v.z + v.w;
    float sq  = v.x*v.x + v.y*v.y + v.z*v.z + v.w*v.w;
#pragma unroll
    for (int o = 16; o > 0; o >>= 1) {
        sum += __shfl_xor_sync(0xffffffffu, sum, o);
        sq  += __shfl_xor_sync(0xffffffffu, sq,  o);
    }
    int warp = tid >> 5, lane = tid & 31;
    if (lane == 0) { ssum[warp] = sum; ssq[warp] = sq; }
    __syncthreads();
    if (tid < 32) {
        float a = (tid < 8) ? ssum[tid] : 0.f;
        float c = (tid < 8) ? ssq [tid] : 0.f;
#pragma unroll
        for (int o = 4; o > 0; o >>= 1) {
            a += __shfl_xor_sync(0xffffffffu, a, o);
            c += __shfl_xor_sync(0xffffffffu, c, o);
        }
        if (tid == 0) { ssum[0] = a; ssq[0] = c; }
    }
    __syncthreads();
    mean = ssum[0] * (1.f / DD);
    float var = ssq[0] * (1.f / DD) - mean * mean;
    rstd = rsqrtf(var + 1e-5f);
}

// layernorm -> bf16 hi/lo pair
__global__ void ln_kernel(const float* __restrict__ x,
                          const float* __restrict__ s,
                          const float* __restrict__ b,
                          bf16* __restrict__ yhi,
                          bf16* __restrict__ ylo)
{
    int row = blockIdx.x, tid = threadIdx.x;
    __shared__ float ssum[8], ssq[8];
    float4 v = ((const float4*)(x + (size_t)row * DD))[tid];
    float mean, rstd;
    ln_stats(v, mean, rstd, ssum, ssq, tid);
    float4 sv = ((const float4*)s)[tid];
    float4 bv = ((const float4*)b)[tid];
    float o0 = (v.x - mean) * rstd * sv.x + bv.x;
    float o1 = (v.y - mean) * rstd * sv.y + bv.y;
    float o2 = (v.z - mean) * rstd * sv.z + bv.z;
    float o3 = (v.w - mean) * rstd * sv.w + bv.w;
    bf16 h0,l0,h1,l1,h2,l2,h3,l3;
    split2(o0,h0,l0); split2(o1,h1,l1); split2(o2,h2,l2); split2(o3,h3,l3);
    uint2 hp, lp;
    hp.x = bf2pack(__bfloat162float(h0), __bfloat162float(h1));
    hp.y = bf2pack(__bfloat162float(h2), __bfloat162float(h3));
    lp.x = bf2pack(__bfloat162float(l0), __bfloat162float(l1));
    lp.y = bf2pack(__bfloat162float(l2), __bfloat162float(l3));
    *(uint2*)&yhi[(size_t)row * DD + tid * 4] = hp;
    *(uint2*)&ylo[(size_t)row * DD + tid * 4] = lp;
}

// final layernorm -> fp16 (single)
__global__ void lnf16_kernel(const float* __restrict__ x,
                             const float* __restrict__ s,
                             const float* __restrict__ b,
                             __half* __restrict__ y)
{
    int row = blockIdx.x, tid = threadIdx.x;
    __shared__ float ssum[8], ssq[8];
    float4 v = ((const float4*)(x + (size_t)row * DD))[tid];
    float mean, rstd;
    ln_stats(v, mean, rstd, ssum, ssq, tid);
    float4 sv = ((const float4*)s)[tid];
    float4 bv = ((const float4*)b)[tid];
    __half2 p0 = __floats2half2_rn((v.x - mean) * rstd * sv.x + bv.x,
                                   (v.y - mean) * rstd * sv.y + bv.y);
    __half2 p1 = __floats2half2_rn((v.z - mean) * rstd * sv.z + bv.z,
                                   (v.w - mean) * rstd * sv.w + bv.w);
    uint2 o;
    o.x = *(uint32_t*)&p0;
    o.y = *(uint32_t*)&p1;
    *(uint2*)&y[(size_t)row * DD + tid * 4] = o;
}

// ---------------- weight transpose + split kernels -------------------------------
__global__ void wconv_kernel(const float* __restrict__ W,
                             uint16_t* __restrict__ Thi, uint16_t* __restrict__ Tlo,
                             int K, int N)
{
    __shared__ float tile[32][33];
    int n0 = blockIdx.x * 32, k0 = blockIdx.y * 32;
    int tx = threadIdx.x, ty = threadIdx.y;
#pragma unroll
    for (int j = 0; j < 32; j += 8)
        tile[ty + j][tx] = W[(size_t)(k0 + ty + j) * N + n0 + tx];
    __syncthreads();
#pragma unroll
    for (int j = 0; j < 32; j += 8) {
        float v = tile[tx][ty + j];
        bf16 hi, lo;
        split2(v, hi, lo);
        size_t o = (size_t)(n0 + ty + j) * K + k0 + tx;
        Thi[o] = *(uint16_t*)&hi; Tlo[o] = *(uint16_t*)&lo;
    }
}

__global__ void wconv16_kernel(const float* __restrict__ W,
                               uint16_t* __restrict__ Thi, uint16_t* __restrict__ Tlo,
                               int K, int N)
{
    __shared__ float tile[32][33];
    int n0 = blockIdx.x * 32, k0 = blockIdx.y * 32;
    int tx = threadIdx.x, ty = threadIdx.y;
#pragma unroll
    for (int j = 0; j < 32; j += 8)
        tile[ty + j][tx] = W[(size_t)(k0 + ty + j) * N + n0 + tx];
    __syncthreads();
#pragma unroll
    for (int j = 0; j < 32; j += 8) {
        float v = tile[tx][ty + j];
        __half hi = __float2half_rn(v);
        __half lo = __float2half_rn(v - __half2float(hi));
        size_t o = (size_t)(n0 + ty + j) * K + k0 + tx;
        Thi[o] = *(uint16_t*)&hi; Tlo[o] = *(uint16_t*)&lo;
    }
}

// ---------------- split GEMM on mma.sync -----------------------------------------
// C[M,N] = A[M,K] @ W[N,K]^T
// NSEG=3 (bf16x3): Ahi*Whi + Ahi*Wlo + Alo*Whi ; NSEG=2 (fp16x2): A*Whi + A*Wlo
// MI: A fragments per warp (2 -> CTA 64 rows, 4 -> CTA 128 rows). CTA cols = 128.
// EPI: 0 = +bias -> C(f32) ; 1 = +bias,GELU -> split(Chi,Clo) ; 2 = +bias+res ; 3 = plain
template<int EPI, int MI, int NSEG, int F16>
__global__ void __launch_bounds__(128, 2)
gemm_mma(const uint16_t* __restrict__ Ahi, const uint16_t* __restrict__ Alo,
         const uint16_t* __restrict__ Whi, const uint16_t* __restrict__ Wlo,
         const float* __restrict__ bias, const float* __restrict__ res,
         float* __restrict__ C, bf16* __restrict__ Chi, bf16* __restrict__ Clo,
         int N, int K)
{
    constexpr int BM = MI * 32;
    constexpr int ST_BYTES = (BM + 128) * 64;   // A: BM rows x 64B, B: 128 rows x 64B
    extern __shared__ char smraw[];
    const uint32_t sbase = smem_u32(smraw);

    const int tid  = threadIdx.x;
    const int wid  = tid >> 5, lane = tid & 31;
    const int bm   = blockIdx.y * BM, bn = blockIdx.x * 128;
    const int wm   = (wid >> 1) * (MI * 16);
    const int wn   = (wid & 1) * 64;

    const int S = (NSEG * K) / 32;

#define LDSTAGE(sidx)                                                                  \
    do {                                                                               \
        int _kg = (sidx) * 32;                                                         \
        int _seg = _kg / K, _ko = _kg - _seg * K;                                      \
        const uint16_t* _As = (NSEG == 2) ? Ahi : ((_seg < 2) ? Ahi : Alo);            \
        const uint16_t* _Ws = (NSEG == 2) ? (_seg ? Wlo : Whi)                         \
                                          : ((_seg == 1) ? Wlo : Whi);                 \
        uint32_t _st = sbase + ((sidx) & 3) * ST_BYTES;                                \
        _Pragma("unroll")                                                              \
        for (int _i = 0; _i < MI; ++_i) {                                              \
            int _id = tid + _i * 128;                                                  \
            int _r = _id >> 2, _lc = _id & 3;                                          \
            int _ph = _lc ^ ((_r >> 1) & 3);                                           \
            cp_async16(_st + _r * 64 + (_ph << 4),                                     \
                       _As + (size_t)(bm + _r) * K + _ko + _lc * 8);                   \
        }                                                                              \
        _Pragma("unroll")                                                              \
        for (int _i = 0; _i < 4; ++_i) {                                               \
            int _id = tid + _i * 128;                                                  \
            int _r = _id >> 2, _lc = _id & 3;                                          \
            int _ph = _lc ^ ((_r >> 1) & 3);                                           \
            cp_async16(_st + BM * 64 + _r * 64 + (_ph << 4),                           \
                       _Ws + (size_t)(bn + _r) * K + _ko + _lc * 8);                   \
        }                                                                              \
        cp_commit();                                                                   \
    } while (0)

    float acc[MI][8][4];
#pragma unroll
    for (int i = 0; i < MI; ++i)
#pragma unroll
        for (int j = 0; j < 8; ++j)
#pragma unroll
            for (int q = 0; q < 4; ++q) acc[i][j][q] = 0.f;

    LDSTAGE(0);
    LDSTAGE(1);

    int arow[MI], asw[MI];
#pragma unroll
    for (int mi = 0; mi < MI; ++mi) {
        int r = wm + mi * 16 + (lane & 15);
        arow[mi] = r * 64;
        asw[mi]  = (r >> 1) & 3;
    }
    int brow[4], bsw[4];
#pragma unroll
    for (int pi = 0; pi < 4; ++pi) {
        int r = wn + pi * 16 + ((lane >> 4) & 1) * 8 + (lane & 7);
        brow[pi] = BM * 64 + r * 64;
        bsw[pi]  = (r >> 1) & 3;
    }
    const int alc0 = (lane >> 4) & 1;
    const int blc0 = (lane >> 3) & 1;

    for (int s = 0; s < S; ++s) {
        cp_wait<1>();
        __syncthreads();
        if (s + 2 < S) LDSTAGE(s + 2);

        const uint32_t st = sbase + (s & 3) * ST_BYTES;
#pragma unroll
        for (int kk = 0; kk < 2; ++kk) {
            uint32_t af[MI][4];
#pragma unroll
            for (int mi = 0; mi < MI; ++mi) {
                int lc = kk * 2 + alc0;
                ldsm4(af[mi][0], af[mi][1], af[mi][2], af[mi][3],
                      st + arow[mi] + ((lc ^ asw[mi]) << 4));
            }
            uint32_t bfr[8][2];
#pragma unroll
            for (int pi = 0; pi < 4; ++pi) {
                int lc = kk * 2 + blc0;
                uint32_t r0, r1, r2, r3;
                ldsm4(r0, r1, r2, r3, st + brow[pi] + ((lc ^ bsw[pi]) << 4));
                bfr[2 * pi][0] = r0;     bfr[2 * pi][1] = r1;
                bfr[2 * pi + 1][0] = r2; bfr[2 * pi + 1][1] = r3;
            }
#pragma unroll
            for (int mi = 0; mi < MI; ++mi)
#pragma unroll
                for (int ni = 0; ni < 8; ++ni)
                    mma_tc<F16>(acc[mi][ni], af[mi], bfr[ni]);
        }
    }
#undef LDSTAGE

    // ---- epilogue ----
    const int r_base = bm + wm + (lane >> 2);
    const int c_base = bn + wn + (lane & 3) * 2;
#pragma unroll
    for (int mi = 0; mi < MI; ++mi) {
#pragma unroll
        for (int ni = 0; ni < 8; ++ni) {
            int col = c_base + ni * 8;
            float b0 = 0.f, b1 = 0.f;
            if (EPI != 3) { b0 = bias[col]; b1 = bias[col + 1]; }
#pragma unroll
            for (int h = 0; h < 2; ++h) {
                int row = r_base + mi * 16 + h * 8;
                float v0 = acc[mi][ni][2 * h]     + b0;
                float v1 = acc[mi][ni][2 * h + 1] + b1;
                if (EPI == 1) {
                    v0 = gelu_exact(v0); v1 = gelu_exact(v1);
                    bf16 h0, l0, h1, l1;
                    split2(v0, h0, l0); split2(v1, h1, l1);
                    *(uint32_t*)&Chi[(size_t)row * N + col] = bf2pack(__bfloat162float(h0), __bfloat162float(h1));
                    *(uint32_t*)&Clo[(size_t)row * N + col] = bf2pack(__bfloat162float(l0), __bfloat162float(l1));
                } else {
                    if (EPI == 2) {
                        v0 += res[(size_t)row * N + col];
                        v1 += res[(size_t)row * N + col + 1];
                    }
                    *(float2*)&C[(size_t)row * N + col] = make_float2(v0, v1);
                }
            }
        }
    }
}

// ---------------- fused causal attention (64-row Q tiles) ------------------------
#define ASTR 68
#define ATT_SMEM (4 * 64 * ASTR * 4)

__global__ void __launch_bounds__(256, 2)
attn_kernel(const float* __restrict__ qkv,
            bf16* __restrict__ ohi, bf16* __restrict__ olo)
{
    extern __shared__ float sm[];
    float* Qs = sm;
    float* Ks = Qs + 64 * ASTR;
    float* Vs = Ks + 64 * ASTR;
    float* Ps = Vs + 64 * ASTR;

    const int tid = threadIdx.x;
    const int bh  = blockIdx.y;
    const int b   = bh >> 4;
    const int hh  = bh & 15;
    const int q0  = blockIdx.x * 64;
    const int tx  = tid & 7;
    const int ty  = tid >> 3;
    const int r0  = ty * 2;
    const int c0  = tx * 8;

    const float* qbase = qkv + ((size_t)(b * TT + q0)) * (3 * DD) + hh * HD;
#pragma unroll
    for (int l = 0; l < 4; ++l) {
        int f = tid + l * 256;
        int r = f >> 4;
        int c = (f & 15) << 2;
        *(float4*)&Qs[r * ASTR + c] = *(const float4*)(qbase + (size_t)r * (3 * DD) + c);
    }

    float m[2], lsum[2], O[2][8];
#pragma unroll
    for (int i = 0; i < 2; ++i) {
        m[i] = -1e30f; lsum[i] = 0.f;
#pragma unroll
        for (int j = 0; j < 8; ++j) O[i][j] = 0.f;
    }

    const int ntiles = blockIdx.x + 1;
    for (int t = 0; t < ntiles; ++t) {
        const int j0 = t * 64;
        __syncthreads();
        const float* kbase = qkv + ((size_t)(b * TT + j0)) * (3 * DD) + DD + hh * HD;
        const float* vbase = kbase + DD;
#pragma unroll
        for (int l = 0; l < 4; ++l) {
            int f = tid + l * 256;
            int r = f >> 4;
            int c = (f & 15) << 2;
            *(float4*)&Ks[r * ASTR + c] = *(const float4*)(kbase + (size_t)r * (3 * DD) + c);
            *(float4*)&Vs[r * ASTR + c] = *(const float4*)(vbase + (size_t)r * (3 * DD) + c);
        }
        __syncthreads();

        float s[2][8] = {};
#pragma unroll
        for (int k4 = 0; k4 < 16; ++k4) {
            float4 qv[2];
#pragma unroll
            for (int i = 0; i < 2; ++i)
                qv[i] = *(const float4*)&Qs[(r0 + i) * ASTR + k4 * 4];
#pragma unroll
            for (int j = 0; j < 8; ++j) {
                float4 kv = *(const float4*)&Ks[(c0 + j) * ASTR + k4 * 4];
#pragma unroll
                for (int i = 0; i < 2; ++i)
                    s[i][j] += qv[i].x * kv.x + qv[i].y * kv.y
                             + qv[i].z * kv.z + qv[i].w * kv.w;
            }
        }

        const bool needmask = (j0 + 63 > q0);
#pragma unroll
        for (int i = 0; i < 2; ++i)
#pragma unroll
            for (int j = 0; j < 8; ++j) {
                float v = s[i][j] * 0.125f;
                if (needmask && (j0 + c0 + j > q0 + r0 + i)) v = -1e30f;
                s[i][j] = v;
            }

        float tm[2];
#pragma unroll
        for (int i = 0; i < 2; ++i) {
            float mx = s[i][0];
#pragma unroll
            for (int j = 1; j < 8; ++j) mx = fmaxf(mx, s[i][j]);
            tm[i] = mx;
        }
#pragma unroll
        for (int o = 1; o < 8; o <<= 1)
#pragma unroll
            for (int i = 0; i < 2; ++i)
                tm[i] = fmaxf(tm[i], __shfl_xor_sync(0xffffffffu, tm[i], o));

        float corr[2], ts[2];
#pragma unroll
        for (int i = 0; i < 2; ++i) {
            float mn = fmaxf(m[i], tm[i]);
            corr[i] = expf(m[i] - mn);
            m[i] = mn;
            ts[i] = 0.f;
#pragma unroll
            for (int j = 0; j < 8; ++j) {
                float p = expf(s[i][j] - mn);
                s[i][j] = p;
                ts[i] += p;
            }
        }
#pragma unroll
        for (int o = 1; o < 8; o <<= 1)
#pragma unroll
            for (int i = 0; i < 2; ++i)
                ts[i] += __shfl_xor_sync(0xffffffffu, ts[i], o);
#pragma unroll
        for (int i = 0; i < 2; ++i) {
            lsum[i] = lsum[i] * corr[i] + ts[i];
#pragma unroll
            for (int j = 0; j < 8; ++j) O[i][j] *= corr[i];
        }

#pragma unroll
        for (int i = 0; i < 2; ++i) {
            *(float4*)&Ps[(r0 + i) * ASTR + c0]     = make_float4(s[i][0], s[i][1], s[i][2], s[i][3]);
            *(float4*)&Ps[(r0 + i) * ASTR + c0 + 4] = make_float4(s[i][4], s[i][5], s[i][6], s[i][7]);
        }
        __syncthreads();

#pragma unroll
        for (int k4 = 0; k4 < 16; ++k4) {
            float p[2][4];
#pragma unroll
            for (int i = 0; i < 2; ++i) {
                float4 pv = *(const float4*)&Ps[(r0 + i) * ASTR + k4 * 4];
                p[i][0] = pv.x; p[i][1] = pv.y; p[i][2] = pv.z; p[i][3] = pv.w;
            }
#pragma unroll
            for (int u = 0; u < 4; ++u) {
                int kv = k4 * 4 + u;
                float4 va = *(const float4*)&Vs[kv * ASTR + c0];
                float4 vb = *(const float4*)&Vs[kv * ASTR + c0 + 4];
#pragma unroll
                for (int i = 0; i < 2; ++i) {
                    float pi = p[i][u];
                    O[i][0] += pi * va.x; O[i][1] += pi * va.y;
                    O[i][2] += pi * va.z; O[i][3] += pi * va.w;
                    O[i][4] += pi * vb.x; O[i][5] += pi * vb.y;
                    O[i][6] += pi * vb.z; O[i][7] += pi * vb.w;
                }
            }
        }
    }

#pragma unroll
    for (int i = 0; i < 2; ++i) {
        float inv = 1.f / lsum[i];
        int qg = q0 + r0 + i;
        size_t off = ((size_t)(b * TT + qg)) * DD + hh * HD + c0;
        float v[8];
#pragma unroll
        for (int j = 0; j < 8; ++j) v[j] = O[i][j] * inv;
        uint4 hp, lp;
        bf16 h0, l0, h1, l1;
        split2(v[0], h0, l0); split2(v[1], h1, l1);
        hp.x = bf2pack(__bfloat162float(h0), __bfloat162float(h1));
        lp.x = bf2pack(__bfloat162float(l0), __bfloat162float(l1));
        split2(v[2], h0, l0); split2(v[3], h1, l1);
        hp.y = bf2pack(__bfloat162float(h0), __bfloat162float(h1));
        lp.y = bf2pack(__bfloat162float(l0), __bfloat162float(l1));
        split2(v[4], h0, l0); split2(v[5], h1, l1);
        hp.z = bf2pack(__bfloat162float(h0), __bfloat162float(h1));
        lp.z = bf2pack(__bfloat162float(l0), __bfloat162float(l1));
        split2(v[6], h0, l0); split2(v[7], h1, l1);
        hp.w = bf2pack(__bfloat162float(h0), __bfloat162float(h1));
        lp.w = bf2pack(__bfloat162float(l0), __bfloat162float(l1));
        *(uint4*)&ohi[off] = hp;
        *(uint4*)&olo[off] = lp;
    }
}

// ---------------- launch ---------------------------------------------------------
extern "C" void kernel_launch(void* const* d_in, const int* in_sizes, int n_in,
                              void* d_out, int out_size)
{
    const int*   idx     = (const int*)  d_in[0];
    const float* tok_emb = (const float*)d_in[1];
    const float* ln1_s   = (const float*)d_in[2];
    const float* ln1_b   = (const float*)d_in[3];
    const float* qkv_w   = (const float*)d_in[4];
    const float* qkv_b   = (const float*)d_in[5];
    const float* out_w   = (const float*)d_in[6];
    const float* out_b   = (const float*)d_in[7];
    const float* ln2_s   = (const float*)d_in[8];
    const float* ln2_b   = (const float*)d_in[9];
    const float* mlp_w1  = (const float*)d_in[10];
    const float* mlp_b1  = (const float*)d_in[11];
    const float* mlp_w2  = (const float*)d_in[12];
    const float* mlp_b2  = (const float*)d_in[13];
    const float* lnf_s   = (const float*)d_in[14];
    const float* lnf_b   = (const float*)d_in[15];
    const float* head_w  = (const float*)d_in[16];
    float* logits = (float*)d_out;

    float *x, *qkv;
    bf16 *ahi, *alo, *m1hi, *m1lo;
    uint16_t *wh, *wl;
    cudaGetSymbolAddress((void**)&x,    g_x);
    cudaGetSymbolAddress((void**)&qkv,  g_qkv);
    cudaGetSymbolAddress((void**)&ahi,  g_ahi);
    cudaGetSymbolAddress((void**)&alo,  g_alo);
    cudaGetSymbolAddress((void**)&m1hi, g_m1hi);
    cudaGetSymbolAddress((void**)&m1lo, g_m1lo);
    cudaGetSymbolAddress((void**)&wh,   g_wh);
    cudaGetSymbolAddress((void**)&wl,   g_wl);

    // smem sizes per tile config
    const int SM_MI2 = 4 * (64 + 128) * 64;    // 49152
    const int SM_MI4 = 4 * (128 + 128) * 64;   // 65536

    cudaFuncSetAttribute((gemm_mma<0,2,3,0>), cudaFuncAttributeMaxDynamicSharedMemorySize, SM_MI2);
    cudaFuncSetAttribute((gemm_mma<2,2,3,0>), cudaFuncAttributeMaxDynamicSharedMemorySize, SM_MI2);
    cudaFuncSetAttribute((gemm_mma<1,4,3,0>), cudaFuncAttributeMaxDynamicSharedMemorySize, SM_MI4);
    cudaFuncSetAttribute((gemm_mma<3,4,2,1>), cudaFuncAttributeMaxDynamicSharedMemorySize, SM_MI4);
    cudaFuncSetAttribute(attn_kernel, cudaFuncAttributeMaxDynamicSharedMemorySize, ATT_SMEM);

    // ---- weight conversion (transpose + split), per launch ----
    for (int l = 0; l < LL; ++l) {
        size_t base = (size_t)l * LW;
        wconv_kernel<<<dim3(3*DD/32, DD/32), dim3(32,8)>>>(
            qkv_w + (size_t)l*DD*3*DD, wh + base, wl + base, DD, 3*DD);
        wconv_kernel<<<dim3(DD/32, DD/32), dim3(32,8)>>>(
            out_w + (size_t)l*DD*DD, wh + base + OFF_OUT, wl + base + OFF_OUT, DD, DD);
        wconv_kernel<<<dim3(FF_/32, DD/32), dim3(32,8)>>>(
            mlp_w1 + (size_t)l*DD*FF_, wh + base + OFF_M1, wl + base + OFF_M1, DD, FF_);
        wconv_kernel<<<dim3(DD/32, FF_/32), dim3(32,8)>>>(
            mlp_w2 + (size_t)l*FF_*DD, wh + base + OFF_M2, wl + base + OFF_M2, FF_, DD);
    }
    wconv16_kernel<<<dim3(VV/32, DD/32), dim3(32,8)>>>(
        head_w, wh + OFF_HD, wl + OFF_HD, DD, VV);

    embed_kernel<<<MM, 256>>>(idx, tok_emb, x);

    for (int l = 0; l < LL; ++l) {
        size_t base = (size_t)l * LW;

        ln_kernel<<<MM, 256>>>(x, ln1_s + (size_t)l*DD, ln1_b + (size_t)l*DD, ahi, alo);

        gemm_mma<0,2,3,0><<<dim3(3*DD/128, MM/64), 128, SM_MI2>>>(
            (uint16_t*)ahi, (uint16_t*)alo, wh + base, wl + base,
            qkv_b + (size_t)l*3*DD, nullptr, qkv, nullptr, nullptr, 3*DD, DD);

        attn_kernel<<<dim3(TT/64, BB*HH), 256, ATT_SMEM>>>(qkv, ahi, alo);

        gemm_mma<2,2,3,0><<<dim3(DD/128, MM/64), 128, SM_MI2>>>(
            (uint16_t*)ahi, (uint16_t*)alo, wh + base + OFF_OUT, wl + base + OFF_OUT,
            out_b + (size_t)l*DD, x, x, nullptr, nullptr, DD, DD);

        ln_kernel<<<MM, 256>>>(x, ln2_s + (size_t)l*DD, ln2_b + (size_t)l*DD, ahi, alo);

        gemm_mma<1,4,3,0><<<dim3(FF_/128, MM/128), 128, SM_MI4>>>(
            (uint16_t*)ahi, (uint16_t*)alo, wh + base + OFF_M1, wl + base + OFF_M1,
            mlp_b1 + (size_t)l*FF_, nullptr, nullptr, m1hi, m1lo, FF_, DD);

        gemm_mma<2,2,3,0><<<dim3(DD/128, MM/64), 128, SM_MI2>>>(
            (uint16_t*)m1hi, (uint16_t*)m1lo, wh + base + OFF_M2, wl + base + OFF_M2,
            mlp_b2 + (size_t)l*DD, x, x, nullptr, nullptr, DD, FF_);
    }

    lnf16_kernel<<<MM, 256>>>(x, lnf_s, lnf_b, (__half*)ahi);

    gemm_mma<3,4,2,1><<<dim3(VV/128, MM/128), 128, SM_MI4>>>(
        (uint16_t*)ahi, (uint16_t*)ahi, wh + OFF_HD, wl + OFF_HD,
        nullptr, nullptr, logits, nullptr, nullptr, VV, DD);
}

// round 6
// speedup vs baseline: 2.6169x; 1.6144x over previous
#include <cuda_runtime.h>
#include <cuda_bf16.h>
#include <cuda_fp16.h>
#include <math.h>
#include <stdint.h>

// Problem constants
#define BB 2
#define TT 1024
#define DD 1024
#define HH 16
#define HD 64
#define FF_ 4096
#define LL 8
#define VV 32000
#define MM (BB*TT)   // 2048

typedef __nv_bfloat16 bf16;

// ---------------- scratch (static device globals; allocation-free) -------------
__device__ float  g_x    [MM * DD];
__device__ __half g_qkv16[MM * 3 * DD];
__device__ bf16   g_ahi  [MM * DD];
__device__ bf16   g_alo  [MM * DD];
__device__ bf16   g_m1hi [MM * FF_];
__device__ bf16   g_m1lo [MM * FF_];

// transposed + split weights, [N,K] row-major per matrix (2-byte elems)
#define LW      12582912ULL
#define OFF_OUT 3145728ULL
#define OFF_M1  4194304ULL
#define OFF_M2  8388608ULL
#define OFF_HD  100663296ULL
#define WTOT    133431296ULL
__device__ uint16_t g_wh[WTOT];
__device__ uint16_t g_wl[WTOT];

// ---------------- helpers -------------------------------------------------------
__device__ __forceinline__ uint32_t smem_u32(const void* p) {
    uint32_t a;
    asm("{ .reg .u64 t; cvta.to.shared.u64 t, %1; cvt.u32.u64 %0, t; }" : "=r"(a) : "l"(p));
    return a;
}
__device__ __forceinline__ void cp_async16(uint32_t saddr, const void* gaddr) {
    asm volatile("cp.async.cg.shared.global [%0], [%1], 16;" :: "r"(saddr), "l"(gaddr));
}
__device__ __forceinline__ void cp_commit() { asm volatile("cp.async.commit_group;"); }
template<int N>
__device__ __forceinline__ void cp_wait() { asm volatile("cp.async.wait_group %0;" :: "n"(N)); }

__device__ __forceinline__ void ldsm4(uint32_t& r0, uint32_t& r1, uint32_t& r2, uint32_t& r3,
                                      uint32_t addr) {
    asm volatile("ldmatrix.sync.aligned.m8n8.x4.shared.b16 {%0,%1,%2,%3}, [%4];"
                 : "=r"(r0), "=r"(r1), "=r"(r2), "=r"(r3) : "r"(addr));
}
__device__ __forceinline__ void ldsm4t(uint32_t& r0, uint32_t& r1, uint32_t& r2, uint32_t& r3,
                                       uint32_t addr) {
    asm volatile("ldmatrix.sync.aligned.m8n8.x4.trans.shared.b16 {%0,%1,%2,%3}, [%4];"
                 : "=r"(r0), "=r"(r1), "=r"(r2), "=r"(r3) : "r"(addr));
}
template<int F16>
__device__ __forceinline__ void mma_tc(float* d, const uint32_t* a, const uint32_t* b) {
    if (F16)
        asm volatile(
            "mma.sync.aligned.m16n8k16.row.col.f32.f16.f16.f32 "
            "{%0,%1,%2,%3}, {%4,%5,%6,%7}, {%8,%9}, {%0,%1,%2,%3};"
            : "+f"(d[0]), "+f"(d[1]), "+f"(d[2]), "+f"(d[3])
            : "r"(a[0]), "r"(a[1]), "r"(a[2]), "r"(a[3]), "r"(b[0]), "r"(b[1]));
    else
        asm volatile(
            "mma.sync.aligned.m16n8k16.row.col.f32.bf16.bf16.f32 "
            "{%0,%1,%2,%3}, {%4,%5,%6,%7}, {%8,%9}, {%0,%1,%2,%3};"
            : "+f"(d[0]), "+f"(d[1]), "+f"(d[2]), "+f"(d[3])
            : "r"(a[0]), "r"(a[1]), "r"(a[2]), "r"(a[3]), "r"(b[0]), "r"(b[1]));
}
__device__ __forceinline__ uint32_t bf2pack(float a, float b) {
    __nv_bfloat162 t = __floats2bfloat162_rn(a, b);
    return *(uint32_t*)&t;
}
__device__ __forceinline__ uint32_t h2pack(float a, float b) {
    __half2 t = __floats2half2_rn(a, b);
    return *(uint32_t*)&t;
}
__device__ __forceinline__ void split2(float v, bf16& h, bf16& l) {
    h = __float2bfloat16_rn(v);
    l = __float2bfloat16_rn(v - __bfloat162float(h));
}
__device__ __forceinline__ float gelu_exact(float x) {
    return 0.5f * x * (1.f + erff(x * 0.7071067811865475f));
}

// ---------------- embed ---------------------------------------------------------
__global__ void embed_kernel(const int* __restrict__ idx,
                             const float* __restrict__ emb,
                             float* __restrict__ x)
{
    int bt  = blockIdx.x;
    int t   = bt & (TT - 1);
    int tok = idx[bt];
    int c0  = threadIdx.x * 4;
    const float kfac = -9.210340371976184f / (float)DD;
#pragma unroll
    for (int u = 0; u < 4; ++u) {
        int c  = c0 + u;
        int i2 = c & ~1;
        float freq = expf((float)i2 * kfac);
        float ang  = (float)t * freq;
        float pe   = (c & 1) ? cosf(ang) : sinf(ang);
        x[(size_t)bt * DD + c] = emb[(size_t)tok * DD + c] + pe;
    }
}

// ---------------- layernorm core ------------------------------------------------
__device__ __forceinline__ void ln_stats(const float4& v, float& mean, float& rstd,
                                         float* ssum, float* ssq, int tid)
{
    float sum = v.x + v.y + v.z + v.w;
    float sq  = v.x*v.x + v.y*v.y + v.z*v.z + v.w*v.w;
#pragma unroll
    for (int o = 16; o > 0; o >>= 1) {
        sum += __shfl_xor_sync(0xffffffffu, sum, o);
        sq  += __shfl_xor_sync(0xffffffffu, sq,  o);
    }
    int warp = tid >> 5, lane = tid & 31;
    if (lane == 0) { ssum[warp] = sum; ssq[warp] = sq; }
    __syncthreads();
    if (tid < 32) {
        float a = (tid < 8) ? ssum[tid] : 0.f;
        float c = (tid < 8) ? ssq [tid] : 0.f;
#pragma unroll
        for (int o = 4; o > 0; o >>= 1) {
            a += __shfl_xor_sync(0xffffffffu, a, o);
            c += __shfl_xor_sync(0xffffffffu, c, o);
        }
        if (tid == 0) { ssum[0] = a; ssq[0] = c; }
    }
    __syncthreads();
    mean = ssum[0] * (1.f / DD);
    float var = ssq[0] * (1.f / DD) - mean * mean;
    rstd = rsqrtf(var + 1e-5f);
}

__global__ void ln_kernel(const float* __restrict__ x,
                          const float* __restrict__ s,
                          const float* __restrict__ b,
                          bf16* __restrict__ yhi,
                          bf16* __restrict__ ylo)
{
    int row = blockIdx.x, tid = threadIdx.x;
    __shared__ float ssum[8], ssq[8];
    float4 v = ((const float4*)(x + (size_t)row * DD))[tid];
    float mean, rstd;
    ln_stats(v, mean, rstd, ssum, ssq, tid);
    float4 sv = ((const float4*)s)[tid];
    float4 bv = ((const float4*)b)[tid];
    float o0 = (v.x - mean) * rstd * sv.x + bv.x;
    float o1 = (v.y - mean) * rstd * sv.y + bv.y;
    float o2 = (v.z - mean) * rstd * sv.z + bv.z;
    float o3 = (v.w - mean) * rstd * sv.w + bv.w;
    bf16 h0,l0,h1,l1,h2,l2,h3,l3;
    split2(o0,h0,l0); split2(o1,h1,l1); split2(o2,h2,l2); split2(o3,h3,l3);
    uint2 hp, lp;
    hp.x = bf2pack(__bfloat162float(h0), __bfloat162float(h1));
    hp.y = bf2pack(__bfloat162float(h2), __bfloat162float(h3));
    lp.x = bf2pack(__bfloat162float(l0), __bfloat162float(l1));
    lp.y = bf2pack(__bfloat162float(l2), __bfloat162float(l3));
    *(uint2*)&yhi[(size_t)row * DD + tid * 4] = hp;
    *(uint2*)&ylo[(size_t)row * DD + tid * 4] = lp;
}

__global__ void lnf16_kernel(const float* __restrict__ x,
                             const float* __restrict__ s,
                             const float* __restrict__ b,
                             __half* __restrict__ y)
{
    int row = blockIdx.x, tid = threadIdx.x;
    __shared__ float ssum[8], ssq[8];
    float4 v = ((const float4*)(x + (size_t)row * DD))[tid];
    float mean, rstd;
    ln_stats(v, mean, rstd, ssum, ssq, tid);
    float4 sv = ((const float4*)s)[tid];
    float4 bv = ((const float4*)b)[tid];
    uint2 o;
    o.x = h2pack((v.x - mean) * rstd * sv.x + bv.x, (v.y - mean) * rstd * sv.y + bv.y);
    o.y = h2pack((v.z - mean) * rstd * sv.z + bv.z, (v.w - mean) * rstd * sv.w + bv.w);
    *(uint2*)&y[(size_t)row * DD + tid * 4] = o;
}

// ---------------- weight transpose + split kernels -------------------------------
__global__ void wconv_kernel(const float* __restrict__ W,
                             uint16_t* __restrict__ Thi, uint16_t* __restrict__ Tlo,
                             int K, int N)
{
    __shared__ float tile[32][33];
    int n0 = blockIdx.x * 32, k0 = blockIdx.y * 32;
    int tx = threadIdx.x, ty = threadIdx.y;
#pragma unroll
    for (int j = 0; j < 32; j += 8)
        tile[ty + j][tx] = W[(size_t)(k0 + ty + j) * N + n0 + tx];
    __syncthreads();
#pragma unroll
    for (int j = 0; j < 32; j += 8) {
        float v = tile[tx][ty + j];
        bf16 hi, lo;
        split2(v, hi, lo);
        size_t o = (size_t)(n0 + ty + j) * K + k0 + tx;
        Thi[o] = *(uint16_t*)&hi; Tlo[o] = *(uint16_t*)&lo;
    }
}

__global__ void wconv16_kernel(const float* __restrict__ W,
                               uint16_t* __restrict__ Thi, uint16_t* __restrict__ Tlo,
                               int K, int N)
{
    __shared__ float tile[32][33];
    int n0 = blockIdx.x * 32, k0 = blockIdx.y * 32;
    int tx = threadIdx.x, ty = threadIdx.y;
#pragma unroll
    for (int j = 0; j < 32; j += 8)
        tile[ty + j][tx] = W[(size_t)(k0 + ty + j) * N + n0 + tx];
    __syncthreads();
#pragma unroll
    for (int j = 0; j < 32; j += 8) {
        float v = tile[tx][ty + j];
        __half hi = __float2half_rn(v);
        __half lo = __float2half_rn(v - __half2float(hi));
        size_t o = (size_t)(n0 + ty + j) * K + k0 + tx;
        Thi[o] = *(uint16_t*)&hi; Tlo[o] = *(uint16_t*)&lo;
    }
}

// ---------------- split GEMM on mma.sync -----------------------------------------
// EPI: 0=+bias->f32 ; 1=+bias,GELU->split(Chi,Clo) ; 2=+bias+res->f32 ; 3=plain->f32 ;
//      4=+bias->fp16 (into Chi reinterpreted as __half*)
template<int EPI, int MI, int NSEG, int F16>
__global__ void __launch_bounds__(128, 2)
gemm_mma(const uint16_t* __restrict__ Ahi, const uint16_t* __restrict__ Alo,
         const uint16_t* __restrict__ Whi, const uint16_t* __restrict__ Wlo,
         const float* __restrict__ bias, const float* __restrict__ res,
         float* __restrict__ C, bf16* __restrict__ Chi, bf16* __restrict__ Clo,
         int N, int K)
{
    constexpr int BM = MI * 32;
    constexpr int ST_BYTES = (BM + 128) * 64;
    extern __shared__ char smraw[];
    const uint32_t sbase = smem_u32(smraw);

    const int tid  = threadIdx.x;
    const int wid  = tid >> 5, lane = tid & 31;
    const int bm   = blockIdx.y * BM, bn = blockIdx.x * 128;
    const int wm   = (wid >> 1) * (MI * 16);
    const int wn   = (wid & 1) * 64;

    const int S = (NSEG * K) / 32;

#define LDSTAGE(sidx)                                                                  \
    do {                                                                               \
        int _kg = (sidx) * 32;                                                         \
        int _seg = _kg / K, _ko = _kg - _seg * K;                                      \
        const uint16_t* _As = (NSEG == 2) ? Ahi : ((_seg < 2) ? Ahi : Alo);            \
        const uint16_t* _Ws = (NSEG == 2) ? (_seg ? Wlo : Whi)                         \
                                          : ((_seg == 1) ? Wlo : Whi);                 \
        uint32_t _st = sbase + ((sidx) & 3) * ST_BYTES;                                \
        _Pragma("unroll")                                                              \
        for (int _i = 0; _i < MI; ++_i) {                                              \
            int _id = tid + _i * 128;                                                  \
            int _r = _id >> 2, _lc = _id & 3;                                          \
            int _ph = _lc ^ ((_r >> 1) & 3);                                           \
            cp_async16(_st + _r * 64 + (_ph << 4),                                     \
                       _As + (size_t)(bm + _r) * K + _ko + _lc * 8);                   \
        }                                                                              \
        _Pragma("unroll")                                                              \
        for (int _i = 0; _i < 4; ++_i) {                                               \
            int _id = tid + _i * 128;                                                  \
            int _r = _id >> 2, _lc = _id & 3;                                          \
            int _ph = _lc ^ ((_r >> 1) & 3);                                           \
            cp_async16(_st + BM * 64 + _r * 64 + (_ph << 4),                           \
                       _Ws + (size_t)(bn + _r) * K + _ko + _lc * 8);                   \
        }                                                                              \
        cp_commit();                                                                   \
    } while (0)

    float acc[MI][8][4];
#pragma unroll
    for (int i = 0; i < MI; ++i)
#pragma unroll
        for (int j = 0; j < 8; ++j)
#pragma unroll
            for (int q = 0; q < 4; ++q) acc[i][j][q] = 0.f;

    LDSTAGE(0);
    LDSTAGE(1);

    int arow[MI], asw[MI];
#pragma unroll
    for (int mi = 0; mi < MI; ++mi) {
        int r = wm + mi * 16 + (lane & 15);
        arow[mi] = r * 64;
        asw[mi]  = (r >> 1) & 3;
    }
    int brow[4], bsw[4];
#pragma unroll
    for (int pi = 0; pi < 4; ++pi) {
        int r = wn + pi * 16 + ((lane >> 4) & 1) * 8 + (lane & 7);
        brow[pi] = BM * 64 + r * 64;
        bsw[pi]  = (r >> 1) & 3;
    }
    const int alc0 = (lane >> 4) & 1;
    const int blc0 = (lane >> 3) & 1;

    for (int s = 0; s < S; ++s) {
        cp_wait<1>();
        __syncthreads();
        if (s + 2 < S) LDSTAGE(s + 2);

        const uint32_t st = sbase + (s & 3) * ST_BYTES;
#pragma unroll
        for (int kk = 0; kk < 2; ++kk) {
            uint32_t af[MI][4];
#pragma unroll
            for (int mi = 0; mi < MI; ++mi) {
                int lc = kk * 2 + alc0;
                ldsm4(af[mi][0], af[mi][1], af[mi][2], af[mi][3],
                      st + arow[mi] + ((lc ^ asw[mi]) << 4));
            }
            uint32_t bfr[8][2];
#pragma unroll
            for (int pi = 0; pi < 4; ++pi) {
                int lc = kk * 2 + blc0;
                uint32_t r0, r1, r2, r3;
                ldsm4(r0, r1, r2, r3, st + brow[pi] + ((lc ^ bsw[pi]) << 4));
                bfr[2 * pi][0] = r0;     bfr[2 * pi][1] = r1;
                bfr[2 * pi + 1][0] = r2; bfr[2 * pi + 1][1] = r3;
            }
#pragma unroll
            for (int mi = 0; mi < MI; ++mi)
#pragma unroll
                for (int ni = 0; ni < 8; ++ni)
                    mma_tc<F16>(acc[mi][ni], af[mi], bfr[ni]);
        }
    }
#undef LDSTAGE

    const int r_base = bm + wm + (lane >> 2);
    const int c_base = bn + wn + (lane & 3) * 2;
#pragma unroll
    for (int mi = 0; mi < MI; ++mi) {
#pragma unroll
        for (int ni = 0; ni < 8; ++ni) {
            int col = c_base + ni * 8;
            float b0 = 0.f, b1 = 0.f;
            if (EPI != 3) { b0 = bias[col]; b1 = bias[col + 1]; }
#pragma unroll
            for (int h = 0; h < 2; ++h) {
                int row = r_base + mi * 16 + h * 8;
                float v0 = acc[mi][ni][2 * h]     + b0;
                float v1 = acc[mi][ni][2 * h + 1] + b1;
                if (EPI == 1) {
                    v0 = gelu_exact(v0); v1 = gelu_exact(v1);
                    bf16 h0, l0, h1, l1;
                    split2(v0, h0, l0); split2(v1, h1, l1);
                    *(uint32_t*)&Chi[(size_t)row * N + col] = bf2pack(__bfloat162float(h0), __bfloat162float(h1));
                    *(uint32_t*)&Clo[(size_t)row * N + col] = bf2pack(__bfloat162float(l0), __bfloat162float(l1));
                } else if (EPI == 4) {
                    *(uint32_t*)&((__half*)Chi)[(size_t)row * N + col] = h2pack(v0, v1);
                } else {
                    if (EPI == 2) {
                        v0 += res[(size_t)row * N + col];
                        v1 += res[(size_t)row * N + col + 1];
                    }
                    *(float2*)&C[(size_t)row * N + col] = make_float2(v0, v1);
                }
            }
        }
    }
}

// ---------------- tensor-core flash attention ------------------------------------
// grid (16 qtiles reversed, B*H), 128 threads. Q tile 64 rows; warp w owns rows 16w..16w+15.
#define ATT2_SMEM (8192 + 2 * 16384)   // Q 8KB + 2 stages x (K 8KB + V 8KB)

__global__ void __launch_bounds__(128, 3)
attn_tc(const __half* __restrict__ qkv, bf16* __restrict__ ohi, bf16* __restrict__ olo)
{
    extern __shared__ char smraw[];
    const uint32_t sQ = smem_u32(smraw);

    const int tid = threadIdx.x;
    const int wid = tid >> 5, lane = tid & 31;
    const int bh  = blockIdx.y;
    const int b   = bh >> 4;
    const int hh  = bh & 15;
    const int qt  = (gridDim.x - 1) - blockIdx.x;   // heavy tiles first
    const int q0  = qt * 64;
    const int wm  = wid * 16;
    const size_t RS = 3 * DD;

    const __half* qbase = qkv + (size_t)(b * TT + q0) * RS + hh * HD;

    // load Q tile (64 x 64 fp16, swizzled 16B chunks)
#pragma unroll
    for (int i = 0; i < 4; ++i) {
        int id = tid + i * 128;
        int r = id >> 3, lc = id & 7, ph = lc ^ (r & 7);
        cp_async16(sQ + r * 128 + (ph << 4), qbase + (size_t)r * RS + lc * 8);
    }

#define LOADKV(t)                                                                      \
    do {                                                                               \
        const __half* kb = qkv + (size_t)(b * TT + (t) * 64) * RS + DD + hh * HD;      \
        uint32_t stK = sQ + 8192 + ((t) & 1) * 16384;                                  \
        _Pragma("unroll")                                                              \
        for (int _i = 0; _i < 4; ++_i) {                                               \
            int _id = tid + _i * 128;                                                  \
            int _r = _id >> 3, _lc = _id & 7, _ph = _lc ^ (_r & 7);                    \
            cp_async16(stK + _r * 128 + (_ph << 4), kb + (size_t)_r * RS + _lc * 8);   \
            cp_async16(stK + 8192 + _r * 128 + (_ph << 4),                             \
                       kb + (size_t)_r * RS + DD + _lc * 8);                           \
        }                                                                              \
        cp_commit();                                                                   \
    } while (0)

    LOADKV(0);
    cp_wait<0>();
    __syncthreads();

    // Q A-fragments (loop invariant)
    uint32_t qf[4][4];
#pragma unroll
    for (int k = 0; k < 4; ++k) {
        int r = wm + (lane & 15);
        int ch = 2 * k + (lane >> 4);
        ldsm4(qf[k][0], qf[k][1], qf[k][2], qf[k][3],
              sQ + r * 128 + ((ch ^ (r & 7)) << 4));
    }

    float m0 = -1e30f, m1 = -1e30f, l0 = 0.f, l1 = 0.f;
    float O[8][4];
#pragma unroll
    for (int n = 0; n < 8; ++n)
#pragma unroll
        for (int q = 0; q < 4; ++q) O[n][q] = 0.f;

    const float SC = 0.125f * 1.4426950408889634f;   // (1/sqrt(64)) * log2(e)
    const int ntiles = qt + 1;

    for (int t = 0; t < ntiles; ++t) {
        if (t > 0) { cp_wait<0>(); __syncthreads(); }
        if (t + 1 < ntiles) LOADKV(t + 1);

        const uint32_t stK = sQ + 8192 + (t & 1) * 16384;
        const uint32_t stV = stK + 8192;

        // S = Q @ K^T  (16 x 64 per warp)
        float s[8][4];
#pragma unroll
        for (int n = 0; n < 8; ++n)
#pragma unroll
            for (int q = 0; q < 4; ++q) s[n][q] = 0.f;
#pragma unroll
        for (int k = 0; k < 4; ++k) {
            uint32_t bfr[8][2];
#pragma unroll
            for (int p = 0; p < 4; ++p) {
                int r = 16 * p + ((lane >> 4) & 1) * 8 + (lane & 7);
                int ch = 2 * k + ((lane >> 3) & 1);
                uint32_t r0, r1, r2, r3;
                ldsm4(r0, r1, r2, r3, stK + r * 128 + ((ch ^ (r & 7)) << 4));
                bfr[2 * p][0] = r0;     bfr[2 * p][1] = r1;
                bfr[2 * p + 1][0] = r2; bfr[2 * p + 1][1] = r3;
            }
#pragma unroll
            for (int n = 0; n < 8; ++n)
                mma_tc<1>(s[n], qf[k], bfr[n]);
        }

        // scale (+ causal mask on diagonal tile), in log2 units
        if (t == ntiles - 1) {
            const int rl0 = wm + (lane >> 2);
            const int cb  = (lane & 3) * 2;
#pragma unroll
            for (int n = 0; n < 8; ++n) {
                int c0g = n * 8 + cb;
                s[n][0] = (c0g     <= rl0    ) ? s[n][0] * SC : -1e30f;
                s[n][1] = (c0g + 1 <= rl0    ) ? s[n][1] * SC : -1e30f;
                s[n][2] = (c0g     <= rl0 + 8) ? s[n][2] * SC : -1e30f;
                s[n][3] = (c0g + 1 <= rl0 + 8) ? s[n][3] * SC : -1e30f;
            }
        } else {
#pragma unroll
            for (int n = 0; n < 8; ++n) {
                s[n][0] *= SC; s[n][1] *= SC; s[n][2] *= SC; s[n][3] *= SC;
            }
        }

        // row max
        float tm0 = -1e30f, tm1 = -1e30f;
#pragma unroll
        for (int n = 0; n < 8; ++n) {
            tm0 = fmaxf(tm0, fmaxf(s[n][0], s[n][1]));
            tm1 = fmaxf(tm1, fmaxf(s[n][2], s[n][3]));
        }
#pragma unroll
        for (int o = 1; o < 4; o <<= 1) {
            tm0 = fmaxf(tm0, __shfl_xor_sync(0xffffffffu, tm0, o));
            tm1 = fmaxf(tm1, __shfl_xor_sync(0xffffffffu, tm1, o));
        }
        float mn0 = fmaxf(m0, tm0), mn1 = fmaxf(m1, tm1);
        float corr0 = exp2f(m0 - mn0), corr1 = exp2f(m1 - mn1);
        m0 = mn0; m1 = mn1;

        // P = exp2(s - mn), pack to fp16 A-frags, accumulate row sums
        float rs0 = 0.f, rs1 = 0.f;
        uint32_t pa[4][4];
#pragma unroll
        for (int k = 0; k < 4; ++k) {
#pragma unroll
            for (int h = 0; h < 2; ++h) {
                int n = 2 * k + h;
                float p0 = exp2f(s[n][0] - mn0);
                float p1 = exp2f(s[n][1] - mn0);
                float p2 = exp2f(s[n][2] - mn1);
                float p3 = exp2f(s[n][3] - mn1);
                rs0 += p0 + p1; rs1 += p2 + p3;
                pa[k][0 + 2 * h] = h2pack(p0, p1);
                pa[k][1 + 2 * h] = h2pack(p2, p3);
            }
        }
#pragma unroll
        for (int o = 1; o < 4; o <<= 1) {
            rs0 += __shfl_xor_sync(0xffffffffu, rs0, o);
            rs1 += __shfl_xor_sync(0xffffffffu, rs1, o);
        }
        l0 = l0 * corr0 + rs0;
        l1 = l1 * corr1 + rs1;
#pragma unroll
        for (int n = 0; n < 8; ++n) {
            O[n][0] *= corr0; O[n][1] *= corr0;
            O[n][2] *= corr1; O[n][3] *= corr1;
        }

        // O += P @ V   (V via ldmatrix.trans)
#pragma unroll
        for (int k = 0; k < 4; ++k) {
            uint32_t vbf[8][2];
#pragma unroll
            for (int p = 0; p < 4; ++p) {
                int r = 16 * k + ((lane >> 3) & 1) * 8 + (lane & 7);
                int ch = 2 * p + (lane >> 4);
                uint32_t r0, r1, r2, r3;
                ldsm4t(r0, r1, r2, r3, stV + r * 128 + ((ch ^ (r & 7)) << 4));
                vbf[2 * p][0] = r0;     vbf[2 * p][1] = r1;
                vbf[2 * p + 1][0] = r2; vbf[2 * p + 1][1] = r3;
            }
#pragma unroll
            for (int n = 0; n < 8; ++n)
                mma_tc<1>(O[n], pa[k], vbf[n]);
        }
    }
#undef LOADKV

    // write normalized output split into bf16 hi/lo
    const float inv0 = 1.f / l0, inv1 = 1.f / l1;
    const int row0 = q0 + wm + (lane >> 2);
    const int cb   = (lane & 3) * 2;
#pragma unroll
    for (int n = 0; n < 8; ++n) {
        int col = n * 8 + cb;
        size_t off0 = ((size_t)(b * TT + row0    )) * DD + hh * HD + col;
        size_t off1 = ((size_t)(b * TT + row0 + 8)) * DD + hh * HD + col;
        float v0 = O[n][0] * inv0, v1 = O[n][1] * inv0;
        float v2 = O[n][2] * inv1, v3 = O[n][3] * inv1;
        bf16 h0, w0, h1, w1;
        split2(v0, h0, w0); split2(v1, h1, w1);
        *(uint32_t*)&ohi[off0] = bf2pack(__bfloat162float(h0), __bfloat162float(h1));
        *(uint32_t*)&olo[off0] = bf2pack(__bfloat162float(w0), __bfloat162float(w1));
        split2(v2, h0, w0); split2(v3, h1, w1);
        *(uint32_t*)&ohi[off1] = bf2pack(__bfloat162float(h0), __bfloat162float(h1));
        *(uint32_t*)&olo[off1] = bf2pack(__bfloat162float(w0), __bfloat162float(w1));
    }
}

// ---------------- launch ---------------------------------------------------------
extern "C" void kernel_launch(void* const* d_in, const int* in_sizes, int n_in,
                              void* d_out, int out_size)
{
    const int*   idx     = (const int*)  d_in[0];
    const float* tok_emb = (const float*)d_in[1];
    const float* ln1_s   = (const float*)d_in[2];
    const float* ln1_b   = (const float*)d_in[3];
    const float* qkv_w   = (const float*)d_in[4];
    const float* qkv_b   = (const float*)d_in[5];
    const float* out_w   = (const float*)d_in[6];
    const float* out_b   = (const float*)d_in[7];
    const float* ln2_s   = (const float*)d_in[8];
    const float* ln2_b   = (const float*)d_in[9];
    const float* mlp_w1  = (const float*)d_in[10];
    const float* mlp_b1  = (const float*)d_in[11];
    const float* mlp_w2  = (const float*)d_in[12];
    const float* mlp_b2  = (const float*)d_in[13];
    const float* lnf_s   = (const float*)d_in[14];
    const float* lnf_b   = (const float*)d_in[15];
    const float* head_w  = (const float*)d_in[16];
    float* logits = (float*)d_out;

    float *x;
    __half *qkv16;
    bf16 *ahi, *alo, *m1hi, *m1lo;
    uint16_t *wh, *wl;
    cudaGetSymbolAddress((void**)&x,     g_x);
    cudaGetSymbolAddress((void**)&qkv16, g_qkv16);
    cudaGetSymbolAddress((void**)&ahi,   g_ahi);
    cudaGetSymbolAddress((void**)&alo,   g_alo);
    cudaGetSymbolAddress((void**)&m1hi,  g_m1hi);
    cudaGetSymbolAddress((void**)&m1lo,  g_m1lo);
    cudaGetSymbolAddress((void**)&wh,    g_wh);
    cudaGetSymbolAddress((void**)&wl,    g_wl);

    const int SM_MI2 = 4 * (64 + 128) * 64;    // 49152
    const int SM_MI4 = 4 * (128 + 128) * 64;   // 65536

    cudaFuncSetAttribute((gemm_mma<4,2,3,0>), cudaFuncAttributeMaxDynamicSharedMemorySize, SM_MI2);
    cudaFuncSetAttribute((gemm_mma<2,2,3,0>), cudaFuncAttributeMaxDynamicSharedMemorySize, SM_MI2);
    cudaFuncSetAttribute((gemm_mma<1,4,3,0>), cudaFuncAttributeMaxDynamicSharedMemorySize, SM_MI4);
    cudaFuncSetAttribute((gemm_mma<3,4,2,1>), cudaFuncAttributeMaxDynamicSharedMemorySize, SM_MI4);
    cudaFuncSetAttribute(attn_tc, cudaFuncAttributeMaxDynamicSharedMemorySize, ATT2_SMEM);

    for (int l = 0; l < LL; ++l) {
        size_t base = (size_t)l * LW;
        wconv_kernel<<<dim3(3*DD/32, DD/32), dim3(32,8)>>>(
            qkv_w + (size_t)l*DD*3*DD, wh + base, wl + base, DD, 3*DD);
        wconv_kernel<<<dim3(DD/32, DD/32), dim3(32,8)>>>(
            out_w + (size_t)l*DD*DD, wh + base + OFF_OUT, wl + base + OFF_OUT, DD, DD);
        wconv_kernel<<<dim3(FF_/32, DD/32), dim3(32,8)>>>(
            mlp_w1 + (size_t)l*DD*FF_, wh + base + OFF_M1, wl + base + OFF_M1, DD, FF_);
        wconv_kernel<<<dim3(DD/32, FF_/32), dim3(32,8)>>>(
            mlp_w2 + (size_t)l*FF_*DD, wh + base + OFF_M2, wl + base + OFF_M2, FF_, DD);
    }
    wconv16_kernel<<<dim3(VV/32, DD/32), dim3(32,8)>>>(
        head_w, wh + OFF_HD, wl + OFF_HD, DD, VV);

    embed_kernel<<<MM, 256>>>(idx, tok_emb, x);

    for (int l = 0; l < LL; ++l) {
        size_t base = (size_t)l * LW;

        ln_kernel<<<MM, 256>>>(x, ln1_s + (size_t)l*DD, ln1_b + (size_t)l*DD, ahi, alo);

        gemm_mma<4,2,3,0><<<dim3(3*DD/128, MM/64), 128, SM_MI2>>>(
            (uint16_t*)ahi, (uint16_t*)alo, wh + base, wl + base,
            qkv_b + (size_t)l*3*DD, nullptr, nullptr, (bf16*)qkv16, nullptr, 3*DD, DD);

        attn_tc<<<dim3(TT/64, BB*HH), 128, ATT2_SMEM>>>(qkv16, ahi, alo);

        gemm_mma<2,2,3,0><<<dim3(DD/128, MM/64), 128, SM_MI2>>>(
            (uint16_t*)ahi, (uint16_t*)alo, wh + base + OFF_OUT, wl + base + OFF_OUT,
            out_b + (size_t)l*DD, x, x, nullptr, nullptr, DD, DD);

        ln_kernel<<<MM, 256>>>(x, ln2_s + (size_t)l*DD, ln2_b + (size_t)l*DD, ahi, alo);

        gemm_mma<1,4,3,0><<<dim3(FF_/128, MM/128), 128, SM_MI4>>>(
            (uint16_t*)ahi, (uint16_t*)alo, wh + base + OFF_M1, wl + base + OFF_M1,
            mlp_b1 + (size_t)l*FF_, nullptr, nullptr, m1hi, m1lo, FF_, DD);

        gemm_mma<2,2,3,0><<<dim3(DD/128, MM/64), 128, SM_MI2>>>(
            (uint16_t*)m1hi, (uint16_t*)m1lo, wh + base + OFF_M2, wl + base + OFF_M2,
            mlp_b2 + (size_t)l*DD, x, x, nullptr, nullptr, DD, FF_);
    }

    lnf16_kernel<<<MM, 256>>>(x, lnf_s, lnf_b, (__half*)ahi);

    gemm_mma<3,4,2,1><<<dim3(VV/128, MM/128), 128, SM_MI4>>>(
        (uint16_t*)ahi, (uint16_t*)ahi, wh + OFF_HD, wl + OFF_HD,
        nullptr, nullptr, logits, nullptr, nullptr, VV, DD);
}

// round 9
// speedup vs baseline: 5.3004x; 2.0255x over previous
#include <cuda_runtime.h>
#include <cuda_bf16.h>
#include <cuda_fp16.h>
#include <math.h>
#include <stdint.h>

// Problem constants
#define BB 2
#define TT 1024
#define DD 1024
#define HH 16
#define HD 64
#define FF_ 4096
#define LL 8
#define VV 32000
#define MM (BB*TT)   // 2048

// ---------------- scratch (static device globals; allocation-free) -------------
__device__ float    g_x    [MM * DD];
__device__ __half   g_qkv16[MM * 3 * DD];
__device__ uint16_t g_ahi  [MM * DD];       // fp16 activation hi
__device__ uint16_t g_alo  [MM * DD];       // fp16 activation lo
__device__ uint16_t g_m1hi [MM * FF_];
__device__ uint16_t g_m1lo [MM * FF_];

// transposed weights, [N,K] row-major per matrix (fp16). Internal: single; head: hi+lo.
#define LW      12582912ULL
#define OFF_OUT 3145728ULL
#define OFF_M1  4194304ULL
#define OFF_M2  8388608ULL
#define OFF_HD  100663296ULL
#define WTOT    133431296ULL
__device__ uint16_t g_wh[WTOT];
__device__ uint16_t g_wl[WTOT];   // only head region used

// ---------------- helpers -------------------------------------------------------
__device__ __forceinline__ uint32_t smem_u32(const void* p) {
    uint32_t a;
    asm("{ .reg .u64 t; cvta.to.shared.u64 t, %1; cvt.u32.u64 %0, t; }" : "=r"(a) : "l"(p));
    return a;
}
__device__ __forceinline__ void cp_async16(uint32_t saddr, const void* gaddr) {
    asm volatile("cp.async.cg.shared.global [%0], [%1], 16;" :: "r"(saddr), "l"(gaddr));
}
__device__ __forceinline__ void cp_commit() { asm volatile("cp.async.commit_group;"); }
template<int N>
__device__ __forceinline__ void cp_wait() { asm volatile("cp.async.wait_group %0;" :: "n"(N)); }

__device__ __forceinline__ void ldsm4(uint32_t& r0, uint32_t& r1, uint32_t& r2, uint32_t& r3,
                                      uint32_t addr) {
    asm volatile("ldmatrix.sync.aligned.m8n8.x4.shared.b16 {%0,%1,%2,%3}, [%4];"
                 : "=r"(r0), "=r"(r1), "=r"(r2), "=r"(r3) : "r"(addr));
}
__device__ __forceinline__ void ldsm4t(uint32_t& r0, uint32_t& r1, uint32_t& r2, uint32_t& r3,
                                       uint32_t addr) {
    asm volatile("ldmatrix.sync.aligned.m8n8.x4.trans.shared.b16 {%0,%1,%2,%3}, [%4];"
                 : "=r"(r0), "=r"(r1), "=r"(r2), "=r"(r3) : "r"(addr));
}
__device__ __forceinline__ void mma_f16(float* d, const uint32_t* a, const uint32_t* b) {
    asm volatile(
        "mma.sync.aligned.m16n8k16.row.col.f32.f16.f16.f32 "
        "{%0,%1,%2,%3}, {%4,%5,%6,%7}, {%8,%9}, {%0,%1,%2,%3};"
        : "+f"(d[0]), "+f"(d[1]), "+f"(d[2]), "+f"(d[3])
        : "r"(a[0]), "r"(a[1]), "r"(a[2]), "r"(a[3]), "r"(b[0]), "r"(b[1]));
}
__device__ __forceinline__ uint32_t h2pack(float a, float b) {
    __half2 t = __floats2half2_rn(a, b);
    return *(uint32_t*)&t;
}
// fp16 hi/lo split: hi = rn_fp16(v), lo = v - hi (exact in fp16 range)
__device__ __forceinline__ void split2h(float v, float& h, float& l) {
    h = __half2float(__float2half_rn(v));
    l = v - h;
}
__device__ __forceinline__ float gelu_exact(float x) {
    return 0.5f * x * (1.f + erff(x * 0.7071067811865475f));
}

// ---------------- embed ---------------------------------------------------------
__global__ void embed_kernel(const int* __restrict__ idx,
                             const float* __restrict__ emb,
                             float* __restrict__ x)
{
    int bt  = blockIdx.x;
    int t   = bt & (TT - 1);
    int tok = idx[bt];
    int c0  = threadIdx.x * 4;
    const float kfac = -9.210340371976184f / (float)DD;
#pragma unroll
    for (int u = 0; u < 4; ++u) {
        int c  = c0 + u;
        int i2 = c & ~1;
        float freq = expf((float)i2 * kfac);
        float ang  = (float)t * freq;
        float pe   = (c & 1) ? cosf(ang) : sinf(ang);
        x[(size_t)bt * DD + c] = emb[(size_t)tok * DD + c] + pe;
    }
}

// ---------------- layernorm core ------------------------------------------------
__device__ __forceinline__ void ln_stats(const float4& v, float& mean, float& rstd,
                                         float* ssum, float* ssq, int tid)
{
    float sum = v.x + v.y + v.z + v.w;
    float sq  = v.x*v.x + v.y*v.y + v.z*v.z + v.w*v.w;
#pragma unroll
    for (int o = 16; o > 0; o >>= 1) {
        sum += __shfl_xor_sync(0xffffffffu, sum, o);
        sq  += __shfl_xor_sync(0xffffffffu, sq,  o);
    }
    int warp = tid >> 5, lane = tid & 31;
    if (lane == 0) { ssum[warp] = sum; ssq[warp] = sq; }
    __syncthreads();
    if (tid < 32) {
        float a = (tid < 8) ? ssum[tid] : 0.f;
        float c = (tid < 8) ? ssq [tid] : 0.f;
#pragma unroll
        for (int o = 4; o > 0; o >>= 1) {
            a += __shfl_xor_sync(0xffffffffu, a, o);
            c += __shfl_xor_sync(0xffffffffu, c, o);
        }
        if (tid == 0) { ssum[0] = a; ssq[0] = c; }
    }
    __syncthreads();
    mean = ssum[0] * (1.f / DD);
    float var = ssq[0] * (1.f / DD) - mean * mean;
    rstd = rsqrtf(var + 1e-5f);
}

// layernorm -> fp16 hi/lo pair
__global__ void ln_kernel(const float* __restrict__ x,
                          const float* __restrict__ s,
                          const float* __restrict__ b,
                          uint16_t* __restrict__ yhi,
                          uint16_t* __restrict__ ylo)
{
    int row = blockIdx.x, tid = threadIdx.x;
    __shared__ float ssum[8], ssq[8];
    float4 v = ((const float4*)(x + (size_t)row * DD))[tid];
    float mean, rstd;
    ln_stats(v, mean, rstd, ssum, ssq, tid);
    float4 sv = ((const float4*)s)[tid];
    float4 bv = ((const float4*)b)[tid];
    float o0 = (v.x - mean) * rstd * sv.x + bv.x;
    float o1 = (v.y - mean) * rstd * sv.y + bv.y;
    float o2 = (v.z - mean) * rstd * sv.z + bv.z;
    float o3 = (v.w - mean) * rstd * sv.w + bv.w;
    float h0,l0,h1,l1,h2,l2,h3,l3;
    split2h(o0,h0,l0); split2h(o1,h1,l1); split2h(o2,h2,l2); split2h(o3,h3,l3);
    uint2 hp, lp;
    hp.x = h2pack(h0, h1); hp.y = h2pack(h2, h3);
    lp.x = h2pack(l0, l1); lp.y = h2pack(l2, l3);
    *(uint2*)&yhi[(size_t)row * DD + tid * 4] = hp;
    *(uint2*)&ylo[(size_t)row * DD + tid * 4] = lp;
}

// final layernorm -> fp16 single
__global__ void lnf16_kernel(const float* __restrict__ x,
                             const float* __restrict__ s,
                             const float* __restrict__ b,
                             uint16_t* __restrict__ y)
{
    int row = blockIdx.x, tid = threadIdx.x;
    __shared__ float ssum[8], ssq[8];
    float4 v = ((const float4*)(x + (size_t)row * DD))[tid];
    float mean, rstd;
    ln_stats(v, mean, rstd, ssum, ssq, tid);
    float4 sv = ((const float4*)s)[tid];
    float4 bv = ((const float4*)b)[tid];
    uint2 o;
    o.x = h2pack((v.x - mean) * rstd * sv.x + bv.x, (v.y - mean) * rstd * sv.y + bv.y);
    o.y = h2pack((v.z - mean) * rstd * sv.z + bv.z, (v.w - mean) * rstd * sv.w + bv.w);
    *(uint2*)&y[(size_t)row * DD + tid * 4] = o;
}

// ---------------- weight transpose kernels ---------------------------------------
// single fp16: W[K,N] -> T[N,K]
__global__ void wconv_h16(const float* __restrict__ W,
                          uint16_t* __restrict__ T, int K, int N)
{
    __shared__ float tile[32][33];
    int n0 = blockIdx.x * 32, k0 = blockIdx.y * 32;
    int tx = threadIdx.x, ty = threadIdx.y;
#pragma unroll
    for (int j = 0; j < 32; j += 8)
        tile[ty + j][tx] = W[(size_t)(k0 + ty + j) * N + n0 + tx];
    __syncthreads();
#pragma unroll
    for (int j = 0; j < 32; j += 8) {
        __half h = __float2half_rn(tile[tx][ty + j]);
        T[(size_t)(n0 + ty + j) * K + k0 + tx] = *(uint16_t*)&h;
    }
}

// fp16 hi/lo split (head)
__global__ void wconv16_kernel(const float* __restrict__ W,
                               uint16_t* __restrict__ Thi, uint16_t* __restrict__ Tlo,
                               int K, int N)
{
    __shared__ float tile[32][33];
    int n0 = blockIdx.x * 32, k0 = blockIdx.y * 32;
    int tx = threadIdx.x, ty = threadIdx.y;
#pragma unroll
    for (int j = 0; j < 32; j += 8)
        tile[ty + j][tx] = W[(size_t)(k0 + ty + j) * N + n0 + tx];
    __syncthreads();
#pragma unroll
    for (int j = 0; j < 32; j += 8) {
        float v = tile[tx][ty + j];
        __half hi = __float2half_rn(v);
        __half lo = __float2half_rn(v - __half2float(hi));
        size_t o = (size_t)(n0 + ty + j) * K + k0 + tx;
        Thi[o] = *(uint16_t*)&hi; Tlo[o] = *(uint16_t*)&lo;
    }
}

// ---------------- split GEMM on fp16 mma.sync -------------------------------------
// 2 segments. ASPLIT=1: (Ahi + Alo) @ W       (activation split, W single)
//             ASPLIT=0:  A @ (Whi + Wlo)      (head: weight split, A single)
// EPI: 0=+bias->f32 ; 1=+bias,GELU->fp16 split(Chi,Clo) ; 2=+bias+res->f32 ;
//      3=plain->f32 ; 4=+bias->fp16 single (C16)
template<int EPI, int MI, int ASPLIT>
__global__ void __launch_bounds__(128, 2)
gemm_mma(const uint16_t* __restrict__ Ahi, const uint16_t* __restrict__ Alo,
         const uint16_t* __restrict__ Whi, const uint16_t* __restrict__ Wlo,
         const float* __restrict__ bias, const float* __restrict__ res,
         float* __restrict__ C, uint16_t* __restrict__ Chi, uint16_t* __restrict__ Clo,
         int N, int K)
{
    constexpr int BM = MI * 32;
    constexpr int ST_BYTES = (BM + 128) * 64;
    extern __shared__ char smraw[];
    const uint32_t sbase = smem_u32(smraw);

    const int tid  = threadIdx.x;
    const int wid  = tid >> 5, lane = tid & 31;
    const int bm   = blockIdx.y * BM, bn = blockIdx.x * 128;
    const int wm   = (wid >> 1) * (MI * 16);
    const int wn   = (wid & 1) * 64;

    const int S = (2 * K) / 32;

#define LDSTAGE(sidx)                                                                  \
    do {                                                                               \
        int _kg = (sidx) * 32;                                                         \
        int _seg = _kg / K, _ko = _kg - _seg * K;                                      \
        const uint16_t* _As = ASPLIT ? (_seg ? Alo : Ahi) : Ahi;                       \
        const uint16_t* _Ws = ASPLIT ? Whi : (_seg ? Wlo : Whi);                       \
        uint32_t _st = sbase + ((sidx) & 3) * ST_BYTES;                                \
        _Pragma("unroll")                                                              \
        for (int _i = 0; _i < MI; ++_i) {                                              \
            int _id = tid + _i * 128;                                                  \
            int _r = _id >> 2, _lc = _id & 3;                                          \
            int _ph = _lc ^ ((_r >> 1) & 3);                                           \
            cp_async16(_st + _r * 64 + (_ph << 4),                                     \
                       _As + (size_t)(bm + _r) * K + _ko + _lc * 8);                   \
        }                                                                              \
        _Pragma("unroll")                                                              \
        for (int _i = 0; _i < 4; ++_i) {                                               \
            int _id = tid + _i * 128;                                                  \
            int _r = _id >> 2, _lc = _id & 3;                                          \
            int _ph = _lc ^ ((_r >> 1) & 3);                                           \
            cp_async16(_st + BM * 64 + _r * 64 + (_ph << 4),                           \
                       _Ws + (size_t)(bn + _r) * K + _ko + _lc * 8);                   \
        }                                                                              \
        cp_commit();                                                                   \
    } while (0)

    float acc[MI][8][4];
#pragma unroll
    for (int i = 0; i < MI; ++i)
#pragma unroll
        for (int j = 0; j < 8; ++j)
#pragma unroll
            for (int q = 0; q < 4; ++q) acc[i][j][q] = 0.f;

    LDSTAGE(0);
    LDSTAGE(1);

    int arow[MI], asw[MI];
#pragma unroll
    for (int mi = 0; mi < MI; ++mi) {
        int r = wm + mi * 16 + (lane & 15);
        arow[mi] = r * 64;
        asw[mi]  = (r >> 1) & 3;
    }
    int brow[4], bsw[4];
#pragma unroll
    for (int pi = 0; pi < 4; ++pi) {
        int r = wn + pi * 16 + ((lane >> 4) & 1) * 8 + (lane & 7);
        brow[pi] = BM * 64 + r * 64;
        bsw[pi]  = (r >> 1) & 3;
    }
    const int alc0 = (lane >> 4) & 1;
    const int blc0 = (lane >> 3) & 1;

    for (int s = 0; s < S; ++s) {
        cp_wait<1>();
        __syncthreads();
        if (s + 2 < S) LDSTAGE(s + 2);

        const uint32_t st = sbase + (s & 3) * ST_BYTES;
#pragma unroll
        for (int kk = 0; kk < 2; ++kk) {
            uint32_t af[MI][4];
#pragma unroll
            for (int mi = 0; mi < MI; ++mi) {
                int lc = kk * 2 + alc0;
                ldsm4(af[mi][0], af[mi][1], af[mi][2], af[mi][3],
                      st + arow[mi] + ((lc ^ asw[mi]) << 4));
            }
            uint32_t bfr[8][2];
#pragma unroll
            for (int pi = 0; pi < 4; ++pi) {
                int lc = kk * 2 + blc0;
                uint32_t r0, r1, r2, r3;
                ldsm4(r0, r1, r2, r3, st + brow[pi] + ((lc ^ bsw[pi]) << 4));
                bfr[2 * pi][0] = r0;     bfr[2 * pi][1] = r1;
                bfr[2 * pi + 1][0] = r2; bfr[2 * pi + 1][1] = r3;
            }
#pragma unroll
            for (int mi = 0; mi < MI; ++mi)
#pragma unroll
                for (int ni = 0; ni < 8; ++ni)
                    mma_f16(acc[mi][ni], af[mi], bfr[ni]);
        }
    }
#undef LDSTAGE

    const int r_base = bm + wm + (lane >> 2);
    const int c_base = bn + wn + (lane & 3) * 2;
#pragma unroll
    for (int mi = 0; mi < MI; ++mi) {
#pragma unroll
        for (int ni = 0; ni < 8; ++ni) {
            int col = c_base + ni * 8;
            float b0 = 0.f, b1 = 0.f;
            if (EPI != 3) { b0 = bias[col]; b1 = bias[col + 1]; }
#pragma unroll
            for (int h = 0; h < 2; ++h) {
                int row = r_base + mi * 16 + h * 8;
                float v0 = acc[mi][ni][2 * h]     + b0;
                float v1 = acc[mi][ni][2 * h + 1] + b1;
                if (EPI == 1) {
                    v0 = gelu_exact(v0); v1 = gelu_exact(v1);
                    float h0, l0, h1, l1;
                    split2h(v0, h0, l0); split2h(v1, h1, l1);
                    *(uint32_t*)&Chi[(size_t)row * N + col] = h2pack(h0, h1);
                    *(uint32_t*)&Clo[(size_t)row * N + col] = h2pack(l0, l1);
                } else if (EPI == 4) {
                    *(uint32_t*)&Chi[(size_t)row * N + col] = h2pack(v0, v1);
                } else {
                    if (EPI == 2) {
                        v0 += res[(size_t)row * N + col];
                        v1 += res[(size_t)row * N + col + 1];
                    }
                    *(float2*)&C[(size_t)row * N + col] = make_float2(v0, v1);
                }
            }
        }
    }
}

// ---------------- tensor-core flash attention ------------------------------------
#define ATT2_SMEM (8192 + 2 * 16384)   // Q 8KB + 2 stages x (K 8KB + V 8KB)

__global__ void __launch_bounds__(128, 3)
attn_tc(const __half* __restrict__ qkv,
        uint16_t* __restrict__ ohi, uint16_t* __restrict__ olo)
{
    extern __shared__ char smraw[];
    const uint32_t sQ = smem_u32(smraw);

    const int tid = threadIdx.x;
    const int wid = tid >> 5, lane = tid & 31;
    const int bh  = blockIdx.y;
    const int b   = bh >> 4;
    const int hh  = bh & 15;
    const int qt  = (gridDim.x - 1) - blockIdx.x;
    const int q0  = qt * 64;
    const int wm  = wid * 16;
    const size_t RS = 3 * DD;

    const __half* qbase = qkv + (size_t)(b * TT + q0) * RS + hh * HD;

#pragma unroll
    for (int i = 0; i < 4; ++i) {
        int id = tid + i * 128;
        int r = id >> 3, lc = id & 7, ph = lc ^ (r & 7);
        cp_async16(sQ + r * 128 + (ph << 4), qbase + (size_t)r * RS + lc * 8);
    }

#define LOADKV(t)                                                                      \
    do {                                                                               \
        const __half* kb = qkv + (size_t)(b * TT + (t) * 64) * RS + DD + hh * HD;      \
        uint32_t stK = sQ + 8192 + ((t) & 1) * 16384;                                  \
        _Pragma("unroll")                                                              \
        for (int _i = 0; _i < 4; ++_i) {                                               \
            int _id = tid + _i * 128;                                                  \
            int _r = _id >> 3, _lc = _id & 7, _ph = _lc ^ (_r & 7);                    \
            cp_async16(stK + _r * 128 + (_ph << 4), kb + (size_t)_r * RS + _lc * 8);   \
            cp_async16(stK + 8192 + _r * 128 + (_ph << 4),                             \
                       kb + (size_t)_r * RS + DD + _lc * 8);                           \
        }                                                                              \
        cp_commit();                                                                   \
    } while (0)

    LOADKV(0);
    cp_wait<0>();
    __syncthreads();

    uint32_t qf[4][4];
#pragma unroll
    for (int k = 0; k < 4; ++k) {
        int r = wm + (lane & 15);
        int ch = 2 * k + (lane >> 4);
        ldsm4(qf[k][0], qf[k][1], qf[k][2], qf[k][3],
              sQ + r * 128 + ((ch ^ (r & 7)) << 4));
    }

    float m0 = -1e30f, m1 = -1e30f, l0 = 0.f, l1 = 0.f;
    float O[8][4];
#pragma unroll
    for (int n = 0; n < 8; ++n)
#pragma unroll
        for (int q = 0; q < 4; ++q) O[n][q] = 0.f;

    const float SC = 0.125f * 1.4426950408889634f;
    const int ntiles = qt + 1;

    for (int t = 0; t < ntiles; ++t) {
        if (t > 0) { cp_wait<0>(); __syncthreads(); }
        if (t + 1 < ntiles) LOADKV(t + 1);

        const uint32_t stK = sQ + 8192 + (t & 1) * 16384;
        const uint32_t stV = stK + 8192;

        float s[8][4];
#pragma unroll
        for (int n = 0; n < 8; ++n)
#pragma unroll
            for (int q = 0; q < 4; ++q) s[n][q] = 0.f;
#pragma unroll
        for (int k = 0; k < 4; ++k) {
            uint32_t bfr[8][2];
#pragma unroll
            for (int p = 0; p < 4; ++p) {
                int r = 16 * p + ((lane >> 4) & 1) * 8 + (lane & 7);
                int ch = 2 * k + ((lane >> 3) & 1);
                uint32_t r0, r1, r2, r3;
                ldsm4(r0, r1, r2, r3, stK + r * 128 + ((ch ^ (r & 7)) << 4));
                bfr[2 * p][0] = r0;     bfr[2 * p][1] = r1;
                bfr[2 * p + 1][0] = r2; bfr[2 * p + 1][1] = r3;
            }
#pragma unroll
            for (int n = 0; n < 8; ++n)
                mma_f16(s[n], qf[k], bfr[n]);
        }

        if (t == ntiles - 1) {
            const int rl0 = wm + (lane >> 2);
            const int cb  = (lane & 3) * 2;
#pragma unroll
            for (int n = 0; n < 8; ++n) {
                int c0g = n * 8 + cb;
                s[n][0] = (c0g     <= rl0    ) ? s[n][0] * SC : -1e30f;
                s[n][1] = (c0g + 1 <= rl0    ) ? s[n][1] * SC : -1e30f;
                s[n][2] = (c0g     <= rl0 + 8) ? s[n][2] * SC : -1e30f;
                s[n][3] = (c0g + 1 <= rl0 + 8) ? s[n][3] * SC : -1e30f;
            }
        } else {
#pragma unroll
            for (int n = 0; n < 8; ++n) {
                s[n][0] *= SC; s[n][1] *= SC; s[n][2] *= SC; s[n][3] *= SC;
            }
        }

        float tm0 = -1e30f, tm1 = -1e30f;
#pragma unroll
        for (int n = 0; n < 8; ++n) {
            tm0 = fmaxf(tm0, fmaxf(s[n][0], s[n][1]));
            tm1 = fmaxf(tm1, fmaxf(s[n][2], s[n][3]));
        }
#pragma unroll
        for (int o = 1; o < 4; o <<= 1) {
            tm0 = fmaxf(tm0, __shfl_xor_sync(0xffffffffu, tm0, o));
            tm1 = fmaxf(tm1, __shfl_xor_sync(0xffffffffu, tm1, o));
        }
        float mn0 = fmaxf(m0, tm0), mn1 = fmaxf(m1, tm1);
        float corr0 = exp2f(m0 - mn0), corr1 = exp2f(m1 - mn1);
        m0 = mn0; m1 = mn1;

        float rs0 = 0.f, rs1 = 0.f;
        uint32_t pa[4][4];
#pragma unroll
        for (int k = 0; k < 4; ++k) {
#pragma unroll
            for (int h = 0; h < 2; ++h) {
                int n = 2 * k + h;
                float p0 = exp2f(s[n][0] - mn0);
                float p1 = exp2f(s[n][1] - mn0);
                float p2 = exp2f(s[n][2] - mn1);
                float p3 = exp2f(s[n][3] - mn1);
                rs0 += p0 + p1; rs1 += p2 + p3;
                pa[k][0 + 2 * h] = h2pack(p0, p1);
                pa[k][1 + 2 * h] = h2pack(p2, p3);
            }
        }
#pragma unroll
        for (int o = 1; o < 4; o <<= 1) {
            rs0 += __shfl_xor_sync(0xffffffffu, rs0, o);
            rs1 += __shfl_xor_sync(0xffffffffu, rs1, o);
        }
        l0 = l0 * corr0 + rs0;
        l1 = l1 * corr1 + rs1;
#pragma unroll
        for (int n = 0; n < 8; ++n) {
            O[n][0] *= corr0; O[n][1] *= corr0;
            O[n][2] *= corr1; O[n][3] *= corr1;
        }

#pragma unroll
        for (int k = 0; k < 4; ++k) {
            uint32_t vbf[8][2];
#pragma unroll
            for (int p = 0; p < 4; ++p) {
                int r = 16 * k + ((lane >> 3) & 1) * 8 + (lane & 7);
                int ch = 2 * p + (lane >> 4);
                uint32_t r0, r1, r2, r3;
                ldsm4t(r0, r1, r2, r3, stV + r * 128 + ((ch ^ (r & 7)) << 4));
                vbf[2 * p][0] = r0;     vbf[2 * p][1] = r1;
                vbf[2 * p + 1][0] = r2; vbf[2 * p + 1][1] = r3;
            }
#pragma unroll
            for (int n = 0; n < 8; ++n)
                mma_f16(O[n], pa[k], vbf[n]);
        }
    }
#undef LOADKV

    const float inv0 = 1.f / l0, inv1 = 1.f / l1;
    const int row0 = q0 + wm + (lane >> 2);
    const int cb   = (lane & 3) * 2;
#pragma unroll
    for (int n = 0; n < 8; ++n) {
        int col = n * 8 + cb;
        size_t off0 = ((size_t)(b * TT + row0    )) * DD + hh * HD + col;
        size_t off1 = ((size_t)(b * TT + row0 + 8)) * DD + hh * HD + col;
        float h0, w0, h1, w1;
        split2h(O[n][0] * inv0, h0, w0); split2h(O[n][1] * inv0, h1, w1);
        *(uint32_t*)&ohi[off0] = h2pack(h0, h1);
        *(uint32_t*)&olo[off0] = h2pack(w0, w1);
        split2h(O[n][2] * inv1, h0, w0); split2h(O[n][3] * inv1, h1, w1);
        *(uint32_t*)&ohi[off1] = h2pack(h0, h1);
        *(uint32_t*)&olo[off1] = h2pack(w0, w1);
    }
}

// ---------------- launch ---------------------------------------------------------
extern "C" void kernel_launch(void* const* d_in, const int* in_sizes, int n_in,
                              void* d_out, int out_size)
{
    const int*   idx     = (const int*)  d_in[0];
    const float* tok_emb = (const float*)d_in[1];
    const float* ln1_s   = (const float*)d_in[2];
    const float* ln1_b   = (const float*)d_in[3];
    const float* qkv_w   = (const float*)d_in[4];
    const float* qkv_b   = (const float*)d_in[5];
    const float* out_w   = (const float*)d_in[6];
    const float* out_b   = (const float*)d_in[7];
    const float* ln2_s   = (const float*)d_in[8];
    const float* ln2_b   = (const float*)d_in[9];
    const float* mlp_w1  = (const float*)d_in[10];
    const float* mlp_b1  = (const float*)d_in[11];
    const float* mlp_w2  = (const float*)d_in[12];
    const float* mlp_b2  = (const float*)d_in[13];
    const float* lnf_s   = (const float*)d_in[14];
    const float* lnf_b   = (const float*)d_in[15];
    const float* head_w  = (const float*)d_in[16];
    float* logits = (float*)d_out;

    float *x;
    __half *qkv16;
    uint16_t *ahi, *alo, *m1hi, *m1lo, *wh, *wl;
    cudaGetSymbolAddress((void**)&x,     g_x);
    cudaGetSymbolAddress((void**)&qkv16, g_qkv16);
    cudaGetSymbolAddress((void**)&ahi,   g_ahi);
    cudaGetSymbolAddress((void**)&alo,   g_alo);
    cudaGetSymbolAddress((void**)&m1hi,  g_m1hi);
    cudaGetSymbolAddress((void**)&m1lo,  g_m1lo);
    cudaGetSymbolAddress((void**)&wh,    g_wh);
    cudaGetSymbolAddress((void**)&wl,    g_wl);

    const int SM_MI2 = 4 * (64 + 128) * 64;    // 49152
    const int SM_MI4 = 4 * (128 + 128) * 64;   // 65536

    cudaFuncSetAttribute((gemm_mma<4,2,1>), cudaFuncAttributeMaxDynamicSharedMemorySize, SM_MI2);
    cudaFuncSetAttribute((gemm_mma<2,2,1>), cudaFuncAttributeMaxDynamicSharedMemorySize, SM_MI2);
    cudaFuncSetAttribute((gemm_mma<1,4,1>), cudaFuncAttributeMaxDynamicSharedMemorySize, SM_MI4);
    cudaFuncSetAttribute((gemm_mma<3,4,0>), cudaFuncAttributeMaxDynamicSharedMemorySize, SM_MI4);
    cudaFuncSetAttribute(attn_tc, cudaFuncAttributeMaxDynamicSharedMemorySize, ATT2_SMEM);

    // ---- weight conversion (transpose + fp16), per launch ----
    for (int l = 0; l < LL; ++l) {
        size_t base = (size_t)l * LW;
        wconv_h16<<<dim3(3*DD/32, DD/32), dim3(32,8)>>>(
            qkv_w + (size_t)l*DD*3*DD, wh + base, DD, 3*DD);
        wconv_h16<<<dim3(DD/32, DD/32), dim3(32,8)>>>(
            out_w + (size_t)l*DD*DD, wh + base + OFF_OUT, DD, DD);
        wconv_h16<<<dim3(FF_/32, DD/32), dim3(32,8)>>>(
            mlp_w1 + (size_t)l*DD*FF_, wh + base + OFF_M1, DD, FF_);
        wconv_h16<<<dim3(DD/32, FF_/32), dim3(32,8)>>>(
            mlp_w2 + (size_t)l*FF_*DD, wh + base + OFF_M2, FF_, DD);
    }
    wconv16_kernel<<<dim3(VV/32, DD/32), dim3(32,8)>>>(
        head_w, wh + OFF_HD, wl + OFF_HD, DD, VV);

    embed_kernel<<<MM, 256>>>(idx, tok_emb, x);

    for (int l = 0; l < LL; ++l) {
        size_t base = (size_t)l * LW;

        ln_kernel<<<MM, 256>>>(x, ln1_s + (size_t)l*DD, ln1_b + (size_t)l*DD, ahi, alo);

        gemm_mma<4,2,1><<<dim3(3*DD/128, MM/64), 128, SM_MI2>>>(
            ahi, alo, wh + base, nullptr,
            qkv_b + (size_t)l*3*DD, nullptr, nullptr, (uint16_t*)qkv16, nullptr, 3*DD, DD);

        attn_tc<<<dim3(TT/64, BB*HH), 128, ATT2_SMEM>>>(qkv16, ahi, alo);

        gemm_mma<2,2,1><<<dim3(DD/128, MM/64), 128, SM_MI2>>>(
            ahi, alo, wh + base + OFF_OUT, nullptr,
            out_b + (size_t)l*DD, x, x, nullptr, nullptr, DD, DD);

        ln_kernel<<<MM, 256>>>(x, ln2_s + (size_t)l*DD, ln2_b + (size_t)l*DD, ahi, alo);

        gemm_mma<1,4,1><<<dim3(FF_/128, MM/128), 128, SM_MI4>>>(
            ahi, alo, wh + base + OFF_M1, nullptr,
            mlp_b1 + (size_t)l*FF_, nullptr, nullptr, m1hi, m1lo, FF_, DD);

        gemm_mma<2,2,1><<<dim3(DD/128, MM/64), 128, SM_MI2>>>(
            m1hi, m1lo, wh + base + OFF_M2, nullptr,
            mlp_b2 + (size_t)l*DD, x, x, nullptr, nullptr, DD, FF_);
    }

    lnf16_kernel<<<MM, 256>>>(x, lnf_s, lnf_b, ahi);

    gemm_mma<3,4,0><<<dim3(VV/128, MM/128), 128, SM_MI4>>>(
        ahi, nullptr, wh + OFF_HD, wl + OFF_HD,
        nullptr, nullptr, logits, nullptr, nullptr, VV, DD);
}

// round 11
// speedup vs baseline: 9.2111x; 1.7378x over previous
#include <cuda_runtime.h>
#include <cuda_bf16.h>
#include <cuda_fp16.h>
#include <math.h>
#include <stdint.h>

// Problem constants
#define BB 2
#define TT 1024
#define DD 1024
#define HH 16
#define HD 64
#define FF_ 4096
#define LL 8
#define VV 32000
#define MM (BB*TT)   // 2048

// ---------------- scratch (static device globals; allocation-free) -------------
__device__ float    g_x    [MM * DD];       // residual stream (fp32)
__device__ __half   g_qkv16[MM * 3 * DD];   // qkv (fp16)
__device__ uint16_t g_a16  [MM * DD];       // fp16 activations (LN out / attn out)
__device__ uint16_t g_m1   [MM * FF_];      // fp16 mlp hidden

// transposed fp16 weights, [N,K] row-major per matrix
#define LW      12582912ULL
#define OFF_OUT 3145728ULL
#define OFF_M1  4194304ULL
#define OFF_M2  8388608ULL
#define OFF_HD  100663296ULL
#define WTOT    133431296ULL
__device__ uint16_t g_wh[WTOT];

// ---------------- helpers -------------------------------------------------------
__device__ __forceinline__ uint32_t smem_u32(const void* p) {
    uint32_t a;
    asm("{ .reg .u64 t; cvta.to.shared.u64 t, %1; cvt.u32.u64 %0, t; }" : "=r"(a) : "l"(p));
    return a;
}
__device__ __forceinline__ void cp_async16(uint32_t saddr, const void* gaddr) {
    asm volatile("cp.async.cg.shared.global [%0], [%1], 16;" :: "r"(saddr), "l"(gaddr));
}
__device__ __forceinline__ void cp_commit() { asm volatile("cp.async.commit_group;"); }
template<int N>
__device__ __forceinline__ void cp_wait() { asm volatile("cp.async.wait_group %0;" :: "n"(N)); }

__device__ __forceinline__ void ldsm4(uint32_t& r0, uint32_t& r1, uint32_t& r2, uint32_t& r3,
                                      uint32_t addr) {
    asm volatile("ldmatrix.sync.aligned.m8n8.x4.shared.b16 {%0,%1,%2,%3}, [%4];"
                 : "=r"(r0), "=r"(r1), "=r"(r2), "=r"(r3) : "r"(addr));
}
__device__ __forceinline__ void ldsm4t(uint32_t& r0, uint32_t& r1, uint32_t& r2, uint32_t& r3,
                                       uint32_t addr) {
    asm volatile("ldmatrix.sync.aligned.m8n8.x4.trans.shared.b16 {%0,%1,%2,%3}, [%4];"
                 : "=r"(r0), "=r"(r1), "=r"(r2), "=r"(r3) : "r"(addr));
}
__device__ __forceinline__ void mma_f16(float* d, const uint32_t* a, const uint32_t* b) {
    asm volatile(
        "mma.sync.aligned.m16n8k16.row.col.f32.f16.f16.f32 "
        "{%0,%1,%2,%3}, {%4,%5,%6,%7}, {%8,%9}, {%0,%1,%2,%3};"
        : "+f"(d[0]), "+f"(d[1]), "+f"(d[2]), "+f"(d[3])
        : "r"(a[0]), "r"(a[1]), "r"(a[2]), "r"(a[3]), "r"(b[0]), "r"(b[1]));
}
__device__ __forceinline__ uint32_t h2pack(float a, float b) {
    __half2 t = __floats2half2_rn(a, b);
    return *(uint32_t*)&t;
}
__device__ __forceinline__ float gelu_exact(float x) {
    return 0.5f * x * (1.f + erff(x * 0.7071067811865475f));
}

// ---------------- embed ---------------------------------------------------------
__global__ void embed_kernel(const int* __restrict__ idx,
                             const float* __restrict__ emb,
                             float* __restrict__ x)
{
    int bt  = blockIdx.x;
    int t   = bt & (TT - 1);
    int tok = idx[bt];
    int c0  = threadIdx.x * 4;
    const float kfac = -9.210340371976184f / (float)DD;
#pragma unroll
    for (int u = 0; u < 4; ++u) {
        int c  = c0 + u;
        int i2 = c & ~1;
        float freq = expf((float)i2 * kfac);
        float ang  = (float)t * freq;
        float pe   = (c & 1) ? cosf(ang) : sinf(ang);
        x[(size_t)bt * DD + c] = emb[(size_t)tok * DD + c] + pe;
    }
}

// ---------------- layernorm -> fp16 ----------------------------------------------
__global__ void ln16_kernel(const float* __restrict__ x,
                            const float* __restrict__ s,
                            const float* __restrict__ b,
                            uint16_t* __restrict__ y)
{
    int row = blockIdx.x, tid = threadIdx.x;
    __shared__ float ssum[8], ssq[8];
    float4 v = ((const float4*)(x + (size_t)row * DD))[tid];
    float sum = v.x + v.y + v.z + v.w;
    float sq  = v.x*v.x + v.y*v.y + v.z*v.z + v.w*v.w;
#pragma unroll
    for (int o = 16; o > 0; o >>= 1) {
        sum += __shfl_xor_sync(0xffffffffu, sum, o);
        sq  += __shfl_xor_sync(0xffffffffu, sq,  o);
    }
    int warp = tid >> 5, lane = tid & 31;
    if (lane == 0) { ssum[warp] = sum; ssq[warp] = sq; }
    __syncthreads();
    if (tid < 32) {
        float a = (tid < 8) ? ssum[tid] : 0.f;
        float c = (tid < 8) ? ssq [tid] : 0.f;
#pragma unroll
        for (int o = 4; o > 0; o >>= 1) {
            a += __shfl_xor_sync(0xffffffffu, a, o);
            c += __shfl_xor_sync(0xffffffffu, c, o);
        }
        if (tid == 0) { ssum[0] = a; ssq[0] = c; }
    }
    __syncthreads();
    float mean = ssum[0] * (1.f / DD);
    float var  = ssq[0]  * (1.f / DD) - mean * mean;
    float rstd = rsqrtf(var + 1e-5f);
    float4 sv = ((const float4*)s)[tid];
    float4 bv = ((const float4*)b)[tid];
    uint2 o;
    o.x = h2pack((v.x - mean) * rstd * sv.x + bv.x, (v.y - mean) * rstd * sv.y + bv.y);
    o.y = h2pack((v.z - mean) * rstd * sv.z + bv.z, (v.w - mean) * rstd * sv.w + bv.w);
    *(uint2*)&y[(size_t)row * DD + tid * 4] = o;
}

// ---------------- weight transpose + fp16: W[K,N] -> T[N,K] ----------------------
// tile stored [n][k]; load coalesced, store 8B vectors along K.
__global__ void wconv_h16(const float* __restrict__ W,
                          uint16_t* __restrict__ T, int K, int N)
{
    __shared__ float tile[32][33];
    int n0 = blockIdx.x * 32, k0 = blockIdx.y * 32;
    int tx = threadIdx.x, ty = threadIdx.y;   // (32, 8)
#pragma unroll
    for (int j = 0; j < 32; j += 8)
        tile[tx][ty + j] = W[(size_t)(k0 + ty + j) * N + n0 + tx];
    __syncthreads();
    int t  = ty * 32 + tx;      // 0..255
    int nl = t >> 3;            // 0..31
    int kg = (t & 7) * 4;       // 0..28
    __half h[4];
#pragma unroll
    for (int i = 0; i < 4; ++i) h[i] = __float2half_rn(tile[nl][kg + i]);
    *(uint2*)&T[(size_t)(n0 + nl) * K + k0 + kg] = *(uint2*)h;
}

// ---------------- plain fp16 GEMM on mma.sync -------------------------------------
// C[M,N] = A[M,K] @ W[N,K]^T, fp32 accum.
// EPI: 0=+bias->f32 ; 1=+bias,GELU->fp16 ; 2=+bias+res->f32 ; 3=plain->f32 ; 4=+bias->fp16
template<int EPI, int MI>
__global__ void __launch_bounds__(128, 2)
gemm_mma(const uint16_t* __restrict__ A, const uint16_t* __restrict__ W,
         const float* __restrict__ bias, const float* __restrict__ res,
         float* __restrict__ C, uint16_t* __restrict__ C16,
         int N, int K)
{
    constexpr int BM = MI * 32;
    constexpr int ST_BYTES = (BM + 128) * 64;
    extern __shared__ char smraw[];
    const uint32_t sbase = smem_u32(smraw);

    const int tid  = threadIdx.x;
    const int wid  = tid >> 5, lane = tid & 31;
    const int bm   = blockIdx.y * BM, bn = blockIdx.x * 128;
    const int wm   = (wid >> 1) * (MI * 16);
    const int wn   = (wid & 1) * 64;

    const int S = K / 32;

#define LDSTAGE(sidx)                                                                  \
    do {                                                                               \
        int _ko = (sidx) * 32;                                                         \
        uint32_t _st = sbase + ((sidx) & 3) * ST_BYTES;                                \
        _Pragma("unroll")                                                              \
        for (int _i = 0; _i < MI; ++_i) {                                              \
            int _id = tid + _i * 128;                                                  \
            int _r = _id >> 2, _lc = _id & 3;                                          \
            int _ph = _lc ^ ((_r >> 1) & 3);                                           \
            cp_async16(_st + _r * 64 + (_ph << 4),                                     \
                       A + (size_t)(bm + _r) * K + _ko + _lc * 8);                     \
        }                                                                              \
        _Pragma("unroll")                                                              \
        for (int _i = 0; _i < 4; ++_i) {                                               \
            int _id = tid + _i * 128;                                                  \
            int _r = _id >> 2, _lc = _id & 3;                                          \
            int _ph = _lc ^ ((_r >> 1) & 3);                                           \
            cp_async16(_st + BM * 64 + _r * 64 + (_ph << 4),                           \
                       W + (size_t)(bn + _r) * K + _ko + _lc * 8);                     \
        }                                                                              \
        cp_commit();                                                                   \
    } while (0)

    float acc[MI][8][4];
#pragma unroll
    for (int i = 0; i < MI; ++i)
#pragma unroll
        for (int j = 0; j < 8; ++j)
#pragma unroll
            for (int q = 0; q < 4; ++q) acc[i][j][q] = 0.f;

    LDSTAGE(0);
    LDSTAGE(1);

    int arow[MI], asw[MI];
#pragma unroll
    for (int mi = 0; mi < MI; ++mi) {
        int r = wm + mi * 16 + (lane & 15);
        arow[mi] = r * 64;
        asw[mi]  = (r >> 1) & 3;
    }
    int brow[4], bsw[4];
#pragma unroll
    for (int pi = 0; pi < 4; ++pi) {
        int r = wn + pi * 16 + ((lane >> 4) & 1) * 8 + (lane & 7);
        brow[pi] = BM * 64 + r * 64;
        bsw[pi]  = (r >> 1) & 3;
    }
    const int alc0 = (lane >> 4) & 1;
    const int blc0 = (lane >> 3) & 1;

    for (int s = 0; s < S; ++s) {
        cp_wait<1>();
        __syncthreads();
        if (s + 2 < S) LDSTAGE(s + 2);

        const uint32_t st = sbase + (s & 3) * ST_BYTES;
#pragma unroll
        for (int kk = 0; kk < 2; ++kk) {
            uint32_t af[MI][4];
#pragma unroll
            for (int mi = 0; mi < MI; ++mi) {
                int lc = kk * 2 + alc0;
                ldsm4(af[mi][0], af[mi][1], af[mi][2], af[mi][3],
                      st + arow[mi] + ((lc ^ asw[mi]) << 4));
            }
            uint32_t bfr[8][2];
#pragma unroll
            for (int pi = 0; pi < 4; ++pi) {
                int lc = kk * 2 + blc0;
                uint32_t r0, r1, r2, r3;
                ldsm4(r0, r1, r2, r3, st + brow[pi] + ((lc ^ bsw[pi]) << 4));
                bfr[2 * pi][0] = r0;     bfr[2 * pi][1] = r1;
                bfr[2 * pi + 1][0] = r2; bfr[2 * pi + 1][1] = r3;
            }
#pragma unroll
            for (int mi = 0; mi < MI; ++mi)
#pragma unroll
                for (int ni = 0; ni < 8; ++ni)
                    mma_f16(acc[mi][ni], af[mi], bfr[ni]);
        }
    }
#undef LDSTAGE

    const int r_base = bm + wm + (lane >> 2);
    const int c_base = bn + wn + (lane & 3) * 2;
#pragma unroll
    for (int mi = 0; mi < MI; ++mi) {
#pragma unroll
        for (int ni = 0; ni < 8; ++ni) {
            int col = c_base + ni * 8;
            float b0 = 0.f, b1 = 0.f;
            if (EPI != 3) { b0 = bias[col]; b1 = bias[col + 1]; }
#pragma unroll
            for (int h = 0; h < 2; ++h) {
                int row = r_base + mi * 16 + h * 8;
                float v0 = acc[mi][ni][2 * h]     + b0;
                float v1 = acc[mi][ni][2 * h + 1] + b1;
                if (EPI == 1) {
                    *(uint32_t*)&C16[(size_t)row * N + col] =
                        h2pack(gelu_exact(v0), gelu_exact(v1));
                } else if (EPI == 4) {
                    *(uint32_t*)&C16[(size_t)row * N + col] = h2pack(v0, v1);
                } else {
                    if (EPI == 2) {
                        v0 += res[(size_t)row * N + col];
                        v1 += res[(size_t)row * N + col + 1];
                    }
                    *(float2*)&C[(size_t)row * N + col] = make_float2(v0, v1);
                }
            }
        }
    }
}

// ---------------- tensor-core flash attention ------------------------------------
#define ATT2_SMEM (8192 + 2 * 16384)   // Q 8KB + 2 stages x (K 8KB + V 8KB)

__global__ void __launch_bounds__(128, 3)
attn_tc(const __half* __restrict__ qkv, uint16_t* __restrict__ out16)
{
    extern __shared__ char smraw[];
    const uint32_t sQ = smem_u32(smraw);

    const int tid = threadIdx.x;
    const int wid = tid >> 5, lane = tid & 31;
    const int bh  = blockIdx.y;
    const int b   = bh >> 4;
    const int hh  = bh & 15;
    const int qt  = (gridDim.x - 1) - blockIdx.x;
    const int q0  = qt * 64;
    const int wm  = wid * 16;
    const size_t RS = 3 * DD;

    const __half* qbase = qkv + (size_t)(b * TT + q0) * RS + hh * HD;

#pragma unroll
    for (int i = 0; i < 4; ++i) {
        int id = tid + i * 128;
        int r = id >> 3, lc = id & 7, ph = lc ^ (r & 7);
        cp_async16(sQ + r * 128 + (ph << 4), qbase + (size_t)r * RS + lc * 8);
    }

#define LOADKV(t)                                                                      \
    do {                                                                               \
        const __half* kb = qkv + (size_t)(b * TT + (t) * 64) * RS + DD + hh * HD;      \
        uint32_t stK = sQ + 8192 + ((t) & 1) * 16384;                                  \
        _Pragma("unroll")                                                              \
        for (int _i = 0; _i < 4; ++_i) {                                               \
            int _id = tid + _i * 128;                                                  \
            int _r = _id >> 3, _lc = _id & 7, _ph = _lc ^ (_r & 7);                    \
            cp_async16(stK + _r * 128 + (_ph << 4), kb + (size_t)_r * RS + _lc * 8);   \
            cp_async16(stK + 8192 + _r * 128 + (_ph << 4),                             \
                       kb + (size_t)_r * RS + DD + _lc * 8);                           \
        }                                                                              \
        cp_commit();                                                                   \
    } while (0)

    LOADKV(0);
    cp_wait<0>();
    __syncthreads();

    uint32_t qf[4][4];
#pragma unroll
    for (int k = 0; k < 4; ++k) {
        int r = wm + (lane & 15);
        int ch = 2 * k + (lane >> 4);
        ldsm4(qf[k][0], qf[k][1], qf[k][2], qf[k][3],
              sQ + r * 128 + ((ch ^ (r & 7)) << 4));
    }

    float m0 = -1e30f, m1 = -1e30f, l0 = 0.f, l1 = 0.f;
    float O[8][4];
#pragma unroll
    for (int n = 0; n < 8; ++n)
#pragma unroll
        for (int q = 0; q < 4; ++q) O[n][q] = 0.f;

    const float SC = 0.125f * 1.4426950408889634f;
    const int ntiles = qt + 1;

    for (int t = 0; t < ntiles; ++t) {
        if (t > 0) { cp_wait<0>(); __syncthreads(); }
        if (t + 1 < ntiles) LOADKV(t + 1);

        const uint32_t stK = sQ + 8192 + (t & 1) * 16384;
        const uint32_t stV = stK + 8192;

        float s[8][4];
#pragma unroll
        for (int n = 0; n < 8; ++n)
#pragma unroll
            for (int q = 0; q < 4; ++q) s[n][q] = 0.f;
#pragma unroll
        for (int k = 0; k < 4; ++k) {
            uint32_t bfr[8][2];
#pragma unroll
            for (int p = 0; p < 4; ++p) {
                int r = 16 * p + ((lane >> 4) & 1) * 8 + (lane & 7);
                int ch = 2 * k + ((lane >> 3) & 1);
                uint32_t r0, r1, r2, r3;
                ldsm4(r0, r1, r2, r3, stK + r * 128 + ((ch ^ (r & 7)) << 4));
                bfr[2 * p][0] = r0;     bfr[2 * p][1] = r1;
                bfr[2 * p + 1][0] = r2; bfr[2 * p + 1][1] = r3;
            }
#pragma unroll
            for (int n = 0; n < 8; ++n)
                mma_f16(s[n], qf[k], bfr[n]);
        }

        if (t == ntiles - 1) {
            const int rl0 = wm + (lane >> 2);
            const int cb  = (lane & 3) * 2;
#pragma unroll
            for (int n = 0; n < 8; ++n) {
                int c0g = n * 8 + cb;
                s[n][0] = (c0g     <= rl0    ) ? s[n][0] * SC : -1e30f;
                s[n][1] = (c0g + 1 <= rl0    ) ? s[n][1] * SC : -1e30f;
                s[n][2] = (c0g     <= rl0 + 8) ? s[n][2] * SC : -1e30f;
                s[n][3] = (c0g + 1 <= rl0 + 8) ? s[n][3] * SC : -1e30f;
            }
        } else {
#pragma unroll
            for (int n = 0; n < 8; ++n) {
                s[n][0] *= SC; s[n][1] *= SC; s[n][2] *= SC; s[n][3] *= SC;
            }
        }

        float tm0 = -1e30f, tm1 = -1e30f;
#pragma unroll
        for (int n = 0; n < 8; ++n) {
            tm0 = fmaxf(tm0, fmaxf(s[n][0], s[n][1]));
            tm1 = fmaxf(tm1, fmaxf(s[n][2], s[n][3]));
        }
#pragma unroll
        for (int o = 1; o < 4; o <<= 1) {
            tm0 = fmaxf(tm0, __shfl_xor_sync(0xffffffffu, tm0, o));
            tm1 = fmaxf(tm1, __shfl_xor_sync(0xffffffffu, tm1, o));
        }
        float mn0 = fmaxf(m0, tm0), mn1 = fmaxf(m1, tm1);
        float corr0 = exp2f(m0 - mn0), corr1 = exp2f(m1 - mn1);
        m0 = mn0; m1 = mn1;

        float rs0 = 0.f, rs1 = 0.f;
        uint32_t pa[4][4];
#pragma unroll
        for (int k = 0; k < 4; ++k) {
#pragma unroll
            for (int h = 0; h < 2; ++h) {
                int n = 2 * k + h;
                float p0 = exp2f(s[n][0] - mn0);
                float p1 = exp2f(s[n][1] - mn0);
                float p2 = exp2f(s[n][2] - mn1);
                float p3 = exp2f(s[n][3] - mn1);
                rs0 += p0 + p1; rs1 += p2 + p3;
                pa[k][0 + 2 * h] = h2pack(p0, p1);
                pa[k][1 + 2 * h] = h2pack(p2, p3);
            }
        }
#pragma unroll
        for (int o = 1; o < 4; o <<= 1) {
            rs0 += __shfl_xor_sync(0xffffffffu, rs0, o);
            rs1 += __shfl_xor_sync(0xffffffffu, rs1, o);
        }
        l0 = l0 * corr0 + rs0;
        l1 = l1 * corr1 + rs1;
#pragma unroll
        for (int n = 0; n < 8; ++n) {
            O[n][0] *= corr0; O[n][1] *= corr0;
            O[n][2] *= corr1; O[n][3] *= corr1;
        }

#pragma unroll
        for (int k = 0; k < 4; ++k) {
            uint32_t vbf[8][2];
#pragma unroll
            for (int p = 0; p < 4; ++p) {
                int r = 16 * k + ((lane >> 3) & 1) * 8 + (lane & 7);
                int ch = 2 * p + (lane >> 4);
                uint32_t r0, r1, r2, r3;
                ldsm4t(r0, r1, r2, r3, stV + r * 128 + ((ch ^ (r & 7)) << 4));
                vbf[2 * p][0] = r0;     vbf[2 * p][1] = r1;
                vbf[2 * p + 1][0] = r2; vbf[2 * p + 1][1] = r3;
            }
#pragma unroll
            for (int n = 0; n < 8; ++n)
                mma_f16(O[n], pa[k], vbf[n]);
        }
    }
#undef LOADKV

    const float inv0 = 1.f / l0, inv1 = 1.f / l1;
    const int row0 = q0 + wm + (lane >> 2);
    const int cb   = (lane & 3) * 2;
#pragma unroll
    for (int n = 0; n < 8; ++n) {
        int col = n * 8 + cb;
        size_t off0 = ((size_t)(b * TT + row0    )) * DD + hh * HD + col;
        size_t off1 = ((size_t)(b * TT + row0 + 8)) * DD + hh * HD + col;
        *(uint32_t*)&out16[off0] = h2pack(O[n][0] * inv0, O[n][1] * inv0);
        *(uint32_t*)&out16[off1] = h2pack(O[n][2] * inv1, O[n][3] * inv1);
    }
}

// ---------------- launch ---------------------------------------------------------
extern "C" void kernel_launch(void* const* d_in, const int* in_sizes, int n_in,
                              void* d_out, int out_size)
{
    const int*   idx     = (const int*)  d_in[0];
    const float* tok_emb = (const float*)d_in[1];
    const float* ln1_s   = (const float*)d_in[2];
    const float* ln1_b   = (const float*)d_in[3];
    const float* qkv_w   = (const float*)d_in[4];
    const float* qkv_b   = (const float*)d_in[5];
    const float* out_w   = (const float*)d_in[6];
    const float* out_b   = (const float*)d_in[7];
    const float* ln2_s   = (const float*)d_in[8];
    const float* ln2_b   = (const float*)d_in[9];
    const float* mlp_w1  = (const float*)d_in[10];
    const float* mlp_b1  = (const float*)d_in[11];
    const float* mlp_w2  = (const float*)d_in[12];
    const float* mlp_b2  = (const float*)d_in[13];
    const float* lnf_s   = (const float*)d_in[14];
    const float* lnf_b   = (const float*)d_in[15];
    const float* head_w  = (const float*)d_in[16];
    float* logits = (float*)d_out;

    float *x;
    __half *qkv16;
    uint16_t *a16, *m1, *wh;
    cudaGetSymbolAddress((void**)&x,     g_x);
    cudaGetSymbolAddress((void**)&qkv16, g_qkv16);
    cudaGetSymbolAddress((void**)&a16,   g_a16);
    cudaGetSymbolAddress((void**)&m1,    g_m1);
    cudaGetSymbolAddress((void**)&wh,    g_wh);

    const int SM_MI2 = 4 * (64 + 128) * 64;    // 49152
    const int SM_MI4 = 4 * (128 + 128) * 64;   // 65536

    cudaFuncSetAttribute((gemm_mma<4,2>), cudaFuncAttributeMaxDynamicSharedMemorySize, SM_MI2);
    cudaFuncSetAttribute((gemm_mma<2,2>), cudaFuncAttributeMaxDynamicSharedMemorySize, SM_MI2);
    cudaFuncSetAttribute((gemm_mma<1,4>), cudaFuncAttributeMaxDynamicSharedMemorySize, SM_MI4);
    cudaFuncSetAttribute((gemm_mma<3,4>), cudaFuncAttributeMaxDynamicSharedMemorySize, SM_MI4);
    cudaFuncSetAttribute(attn_tc, cudaFuncAttributeMaxDynamicSharedMemorySize, ATT2_SMEM);

    // ---- weight conversion (transpose + fp16), per launch ----
    for (int l = 0; l < LL; ++l) {
        size_t base = (size_t)l * LW;
        wconv_h16<<<dim3(3*DD/32, DD/32), dim3(32,8)>>>(
            qkv_w + (size_t)l*DD*3*DD, wh + base, DD, 3*DD);
        wconv_h16<<<dim3(DD/32, DD/32), dim3(32,8)>>>(
            out_w + (size_t)l*DD*DD, wh + base + OFF_OUT, DD, DD);
        wconv_h16<<<dim3(FF_/32, DD/32), dim3(32,8)>>>(
            mlp_w1 + (size_t)l*DD*FF_, wh + base + OFF_M1, DD, FF_);
        wconv_h16<<<dim3(DD/32, FF_/32), dim3(32,8)>>>(
            mlp_w2 + (size_t)l*FF_*DD, wh + base + OFF_M2, FF_, DD);
    }
    wconv_h16<<<dim3(VV/32, DD/32), dim3(32,8)>>>(head_w, wh + OFF_HD, DD, VV);

    embed_kernel<<<MM, 256>>>(idx, tok_emb, x);

    for (int l = 0; l < LL; ++l) {
        size_t base = (size_t)l * LW;

        ln16_kernel<<<MM, 256>>>(x, ln1_s + (size_t)l*DD, ln1_b + (size_t)l*DD, a16);

        gemm_mma<4,2><<<dim3(3*DD/128, MM/64), 128, SM_MI2>>>(
            a16, wh + base, qkv_b + (size_t)l*3*DD, nullptr,
            nullptr, (uint16_t*)qkv16, 3*DD, DD);

        attn_tc<<<dim3(TT/64, BB*HH), 128, ATT2_SMEM>>>(qkv16, a16);

        gemm_mma<2,2><<<dim3(DD/128, MM/64), 128, SM_MI2>>>(
            a16, wh + base + OFF_OUT, out_b + (size_t)l*DD, x,
            x, nullptr, DD, DD);

        ln16_kernel<<<MM, 256>>>(x, ln2_s + (size_t)l*DD, ln2_b + (size_t)l*DD, a16);

        gemm_mma<1,4><<<dim3(FF_/128, MM/128), 128, SM_MI4>>>(
            a16, wh + base + OFF_M1, mlp_b1 + (size_t)l*FF_, nullptr,
            nullptr, m1, FF_, DD);

        gemm_mma<2,2><<<dim3(DD/128, MM/64), 128, SM_MI2>>>(
            m1, wh + base + OFF_M2, mlp_b2 + (size_t)l*DD, x,
            x, nullptr, DD, FF_);
    }

    ln16_kernel<<<MM, 256>>>(x, lnf_s, lnf_b, a16);

    gemm_mma<3,4><<<dim3(VV/128, MM/128), 128, SM_MI4>>>(
        a16, wh + OFF_HD, nullptr, nullptr,
        logits, nullptr, VV, DD);
}